// round 11
// baseline (speedup 1.0000x reference)
#include <cuda_runtime.h>
#include <cuda_fp16.h>
#include <cstdint>

#define B  32
#define T  1024
#define D  512
#define KW 3

// ---- conv GEMM tiles ----
#define BM 128
#define BN 256
#define BK 32
#define XS 40            // Xs row stride in fp16 (80B: conflict-free for ldmatrix)
#define WS 264           // Ws row stride in fp16 (528B = 16*33: conflict-free for ldmatrix.trans)
#define CONV_THREADS 256
#define NCHUNK (D / BK)  // 16
#define NSTAGE 3

// dynamic smem: three stages, each = [X plane][W plane]
#define X_PLANE ((BM + 2) * XS * 2)          // 10400 B
#define W_PLANE (KW * BK * WS * 2)           // 50688 B
#define STAGE   (X_PLANE + W_PLANE)          // 61088 B
#define SM_TOTAL (NSTAGE * STAGE)            // 183264 B

// ---- scratch (no runtime allocation allowed) ----
__device__ float  g_conv[(size_t)B * T * D];    // fp32 conv output
__device__ __half g_x1[(size_t)B * T * D];      // enc fp16
__device__ __half g_x2[(size_t)B * T * D];      // LN1 out fp16
__device__ __half g_w1h[KW * D * D];            // weights fp16 (native HIO)
__device__ __half g_w2h[KW * D * D];
__device__ int    g_cum[B * T];

__device__ __forceinline__ uint32_t smem_u32(const void* p) {
    uint32_t a;
    asm("{ .reg .u64 t; cvta.to.shared.u64 t, %1; cvt.u32.u64 %0, t; }" : "=r"(a) : "l"(p));
    return a;
}
__device__ __forceinline__ void cp16(uint32_t dst, const void* src, int szbytes) {
    asm volatile("cp.async.cg.shared.global [%0], [%1], 16, %2;"
                 :: "r"(dst), "l"(src), "r"(szbytes));
}

// ================= conv1d(k=3,SAME) + bias + relu, fp16 mma.sync ===========
// CTA tile 128(M t-rows) x 256(N channels); 8 warps 2x4; warp tile 64x64.
__global__ void __launch_bounds__(CONV_THREADS)
conv_mma_kernel(const __half* __restrict__ x,
                const __half* __restrict__ w,   // [tap][c][n]
                const float* __restrict__ bias,
                float* __restrict__ y) {
    extern __shared__ __align__(16) char smem[];

    const int tid  = threadIdx.x;
    const int lane = tid & 31;
    const int wid  = tid >> 5;
    const int wm   = wid >> 2;     // 0..1 -> m offset wm*64
    const int wn   = wid & 3;      // 0..3 -> n offset wn*64
    const int t0   = blockIdx.x * BM;
    const int n0   = blockIdx.y * BN;
    const int b    = blockIdx.z;

    float c[4][8][4];
#pragma unroll
    for (int mt = 0; mt < 4; mt++)
#pragma unroll
        for (int nt = 0; nt < 8; nt++)
#pragma unroll
            for (int i = 0; i < 4; i++) c[mt][nt][i] = 0.f;

    const uint32_t sb = smem_u32(smem);
    const uint32_t a_off = (uint32_t)(((wm * 64 + (lane & 15)) * XS + (lane >> 4) * 8) * 2);
    const uint32_t b_off = (uint32_t)(X_PLANE +
                                      ((lane & 15) * WS + wn * 64 + (lane >> 4) * 8) * 2);

    // ---- async tile loader for chunk c0 into stage st ----
    auto load_chunk = [&](int st, int c0) {
        const uint32_t stb = sb + (uint32_t)(st * STAGE);
        // X plane: 520 16B vectors (row r <-> t = t0 + r - 1, zero pad)
#pragma unroll
        for (int i = 0; i < 3; i++) {
            int idx = tid + i * CONV_THREADS;
            if (idx < (BM + 2) * 4) {
                int row = idx >> 2, u = idx & 3;
                int t = t0 + row - 1;
                int ok = (t >= 0 && t < T);
                int tc = ok ? t : 0;
                cp16(stb + (uint32_t)((row * XS + u * 8) * 2),
                     x + ((size_t)(b * T + tc) * D + c0 + u * 8),
                     ok ? 16 : 0);
            }
        }
        // W plane: [tap][k 0..31][n 0..255], 96 rows x 32 vectors
        const uint32_t wbsm = stb + (uint32_t)X_PLANE;
#pragma unroll
        for (int i = 0; i < 12; i++) {
            int idx = tid + i * CONV_THREADS;      // 0..3071
            int r = idx >> 5, u = idx & 31;        // r = tap*32+k
            int tap = r >> 5, k = r & 31;
            cp16(wbsm + (uint32_t)((r * WS + u * 8) * 2),
                 w + ((size_t)(tap * D + c0 + k) * D + n0 + u * 8), 16);
        }
        asm volatile("cp.async.commit_group;");
    };

    load_chunk(0, 0);
    load_chunk(1, BK);

#pragma unroll 1
    for (int it = 0; it < NCHUNK; it++) {
        const int st = it % NSTAGE;
        // ensure stage st's loads have landed
        if (it < NCHUNK - 1)
            asm volatile("cp.async.wait_group 1;");
        else
            asm volatile("cp.async.wait_group 0;");
        __syncthreads();   // also: all warps finished computing on stage (it+2)%3

        if (it + 2 < NCHUNK)
            load_chunk((it + 2) % NSTAGE, (it + 2) * BK);

        const uint32_t abase = sb + (uint32_t)(st * STAGE) + a_off;
        const uint32_t bbase = sb + (uint32_t)(st * STAGE) + b_off;

#pragma unroll
        for (int tap = 0; tap < KW; tap++) {
#pragma unroll
            for (int ks = 0; ks < 2; ks++) {
                uint32_t a[4][4];
#pragma unroll
                for (int mt = 0; mt < 4; mt++) {
                    uint32_t addr = abase + (uint32_t)((mt * 16 + tap) * XS * 2 + ks * 32);
                    asm volatile(
                        "ldmatrix.sync.aligned.m8n8.x4.shared.b16 {%0,%1,%2,%3}, [%4];"
                        : "=r"(a[mt][0]), "=r"(a[mt][1]), "=r"(a[mt][2]), "=r"(a[mt][3])
                        : "r"(addr));
                }
                uint32_t bf[4][4];
#pragma unroll
                for (int q = 0; q < 4; q++) {
                    uint32_t addr = bbase +
                        (uint32_t)((tap * 32 + ks * 16) * WS * 2 + q * 32);
                    asm volatile(
                        "ldmatrix.sync.aligned.m8n8.x4.trans.shared.b16 {%0,%1,%2,%3}, [%4];"
                        : "=r"(bf[q][0]), "=r"(bf[q][1]), "=r"(bf[q][2]), "=r"(bf[q][3])
                        : "r"(addr));
                }
#pragma unroll
                for (int mt = 0; mt < 4; mt++)
#pragma unroll
                    for (int nt = 0; nt < 8; nt++) {
                        int q = nt >> 1, h = (nt & 1) * 2;
                        asm volatile(
                            "mma.sync.aligned.m16n8k16.row.col.f32.f16.f16.f32 "
                            "{%0,%1,%2,%3}, {%4,%5,%6,%7}, {%8,%9}, {%0,%1,%2,%3};"
                            : "+f"(c[mt][nt][0]), "+f"(c[mt][nt][1]),
                              "+f"(c[mt][nt][2]), "+f"(c[mt][nt][3])
                            : "r"(a[mt][0]), "r"(a[mt][1]), "r"(a[mt][2]), "r"(a[mt][3]),
                              "r"(bf[q][h]), "r"(bf[q][h + 1]));
                    }
            }
        }
    }

    // ---- epilogue: bias + relu, fp32 store ----
    const int gid = lane >> 2, tig = lane & 3;
#pragma unroll
    for (int mt = 0; mt < 4; mt++) {
        int row0 = t0 + wm * 64 + mt * 16 + gid;
#pragma unroll
        for (int nt = 0; nt < 8; nt++) {
            int col = n0 + wn * 64 + nt * 8 + tig * 2;
            float bx = bias[col], by = bias[col + 1];
            float2 o0, o1;
            o0.x = fmaxf(c[mt][nt][0] + bx, 0.f);
            o0.y = fmaxf(c[mt][nt][1] + by, 0.f);
            o1.x = fmaxf(c[mt][nt][2] + bx, 0.f);
            o1.y = fmaxf(c[mt][nt][3] + by, 0.f);
            *reinterpret_cast<float2*>(y + ((size_t)(b * T + row0)) * D + col) = o0;
            *reinterpret_cast<float2*>(y + ((size_t)(b * T + row0 + 8)) * D + col) = o1;
        }
    }
}

// ================= fp32 -> fp16 =================
__global__ void __launch_bounds__(256)
cvt_half_kernel(const float4* __restrict__ x, uint2* __restrict__ y, int n4) {
    int i = blockIdx.x * 256 + threadIdx.x;
    if (i < n4) {
        float4 v = x[i];
        __half2 a = __floats2half2_rn(v.x, v.y);
        __half2 b = __floats2half2_rn(v.z, v.w);
        uint2 o;
        o.x = reinterpret_cast<const unsigned&>(a);
        o.y = reinterpret_cast<const unsigned&>(b);
        y[i] = o;
    }
}

// ================= LayerNorm (fp32 in) -> fp16 out =================
__global__ void __launch_bounds__(256)
ln_half_kernel(const float* __restrict__ x, const float* __restrict__ gw,
               const float* __restrict__ gb, __half* __restrict__ y) {
    const int row  = blockIdx.x * 8 + (threadIdx.x >> 5);
    const int lane = threadIdx.x & 31;
    const float4* xr = reinterpret_cast<const float4*>(x) + (size_t)row * (D / 4);
    float4 v[4];
    float s = 0.f, sq = 0.f;
#pragma unroll
    for (int i = 0; i < 4; i++) {
        float4 t = xr[i * 32 + lane];
        v[i] = t;
        s  += t.x + t.y + t.z + t.w;
        sq += t.x * t.x + t.y * t.y + t.z * t.z + t.w * t.w;
    }
#pragma unroll
    for (int o = 16; o > 0; o >>= 1) {
        s  += __shfl_xor_sync(0xffffffffu, s, o);
        sq += __shfl_xor_sync(0xffffffffu, sq, o);
    }
    const float mu = s * (1.0f / D);
    const float rs = rsqrtf(sq * (1.0f / D) - mu * mu + 1e-5f);
    const float4* gv = reinterpret_cast<const float4*>(gw);
    const float4* bv = reinterpret_cast<const float4*>(gb);
    uint2* yr = reinterpret_cast<uint2*>(y + (size_t)row * D);
#pragma unroll
    for (int i = 0; i < 4; i++) {
        float4 g = gv[i * 32 + lane], bb = bv[i * 32 + lane], t = v[i];
        float4 o;
        o.x = (t.x - mu) * rs * g.x + bb.x;
        o.y = (t.y - mu) * rs * g.y + bb.y;
        o.z = (t.z - mu) * rs * g.z + bb.z;
        o.w = (t.w - mu) * rs * g.w + bb.w;
        __half2 p0 = __floats2half2_rn(o.x, o.y);
        __half2 p1 = __floats2half2_rn(o.z, o.w);
        uint2 u;
        u.x = reinterpret_cast<const unsigned&>(p0);
        u.y = reinterpret_cast<const unsigned&>(p1);
        yr[i * 32 + lane] = u;
    }
}

// ================= LayerNorm + linear(512->1) fused =================
__global__ void __launch_bounds__(256)
ln_linear_kernel(const float* __restrict__ x, const float* __restrict__ gw,
                 const float* __restrict__ gb, const float* __restrict__ lw,
                 const float* __restrict__ lb, float* __restrict__ dur_out) {
    const int row  = blockIdx.x * 8 + (threadIdx.x >> 5);
    const int lane = threadIdx.x & 31;
    const float4* xr = reinterpret_cast<const float4*>(x) + (size_t)row * (D / 4);
    float4 v[4];
    float s = 0.f, sq = 0.f;
#pragma unroll
    for (int i = 0; i < 4; i++) {
        float4 t = xr[i * 32 + lane];
        v[i] = t;
        s  += t.x + t.y + t.z + t.w;
        sq += t.x * t.x + t.y * t.y + t.z * t.z + t.w * t.w;
    }
#pragma unroll
    for (int o = 16; o > 0; o >>= 1) {
        s  += __shfl_xor_sync(0xffffffffu, s, o);
        sq += __shfl_xor_sync(0xffffffffu, sq, o);
    }
    const float mu = s * (1.0f / D);
    const float rs = rsqrtf(sq * (1.0f / D) - mu * mu + 1e-5f);
    const float4* gv = reinterpret_cast<const float4*>(gw);
    const float4* bv = reinterpret_cast<const float4*>(gb);
    const float4* wv = reinterpret_cast<const float4*>(lw);
    float dot = 0.f;
#pragma unroll
    for (int i = 0; i < 4; i++) {
        float4 g = gv[i * 32 + lane], bb = bv[i * 32 + lane];
        float4 w = wv[i * 32 + lane], t = v[i];
        dot += ((t.x - mu) * rs * g.x + bb.x) * w.x;
        dot += ((t.y - mu) * rs * g.y + bb.y) * w.y;
        dot += ((t.z - mu) * rs * g.z + bb.z) * w.z;
        dot += ((t.w - mu) * rs * g.w + bb.w) * w.w;
    }
#pragma unroll
    for (int o = 16; o > 0; o >>= 1)
        dot += __shfl_xor_sync(0xffffffffu, dot, o);
    if (lane == 0) dur_out[row] = dot + lb[0];
}

// ================= per-batch inclusive cumsum =================
__global__ void __launch_bounds__(T)
cumsum_kernel(const int* __restrict__ dur, int* __restrict__ cum) {
    __shared__ int s[T];
    const int b = blockIdx.x, t = threadIdx.x;
    s[t] = dur[b * T + t];
    __syncthreads();
#pragma unroll
    for (int off = 1; off < T; off <<= 1) {
        int add = (t >= off) ? s[t - off] : 0;
        __syncthreads();
        s[t] += add;
        __syncthreads();
    }
    cum[b * T + t] = s[t];
}

// ================= length-regulation gather =================
__global__ void __launch_bounds__(128)
expand_kernel(const float* __restrict__ enc, const int* __restrict__ cum,
              float* __restrict__ out, int max_len) {
    const int j    = blockIdx.x;
    const int b    = blockIdx.y;
    const int lane = threadIdx.x;
    const int* c = cum + b * T;
    const int total = c[T - 1];
    float4 v = make_float4(0.f, 0.f, 0.f, 0.f);
    if (j < total) {
        int lo = 0, hi = T - 1;
        while (lo < hi) {
            int mid = (lo + hi) >> 1;
            if (c[mid] > j) hi = mid; else lo = mid + 1;
        }
        v = reinterpret_cast<const float4*>(enc + (size_t)(b * T + lo) * D)[lane];
    }
    reinterpret_cast<float4*>(out + ((size_t)b * max_len + j) * D)[lane] = v;
}

extern "C" void kernel_launch(void* const* d_in, const int* in_sizes, int n_in,
                              void* d_out, int out_size) {
    const float* enc = (const float*)d_in[0];
    const int*   dur = (const int*)d_in[1];
    const float* w1  = (const float*)d_in[2];
    const float* b1  = (const float*)d_in[3];
    const float* g1  = (const float*)d_in[4];
    const float* be1 = (const float*)d_in[5];
    const float* w2  = (const float*)d_in[6];
    const float* b2  = (const float*)d_in[7];
    const float* g2  = (const float*)d_in[8];
    const float* be2 = (const float*)d_in[9];
    const float* lw  = (const float*)d_in[10];
    const float* lb  = (const float*)d_in[11];

    const int max_len = (out_size - B * T) / (B * D);
    float* out     = (float*)d_out;
    float* dur_out = out + (size_t)B * max_len * D;

    float* cbuf;    cudaGetSymbolAddress((void**)&cbuf, g_conv);
    __half *x1, *x2, *w1h, *w2h;
    cudaGetSymbolAddress((void**)&x1, g_x1);
    cudaGetSymbolAddress((void**)&x2, g_x2);
    cudaGetSymbolAddress((void**)&w1h, g_w1h);
    cudaGetSymbolAddress((void**)&w2h, g_w2h);
    int* cm;        cudaGetSymbolAddress((void**)&cm, g_cum);

    cudaFuncSetAttribute(conv_mma_kernel,
                         cudaFuncAttributeMaxDynamicSharedMemorySize, SM_TOTAL);

    // conversions: enc + weights to fp16 (native layouts)
    const int nx4 = (B * T * D) / 4;
    cvt_half_kernel<<<nx4 / 256, 256>>>((const float4*)enc, (uint2*)x1, nx4);
    const int nw4 = (KW * D * D) / 4;
    cvt_half_kernel<<<(nw4 + 255) / 256, 256>>>((const float4*)w1, (uint2*)w1h, nw4);
    cvt_half_kernel<<<(nw4 + 255) / 256, 256>>>((const float4*)w2, (uint2*)w2h, nw4);

    dim3 cgrid(T / BM, D / BN, B);   // (8, 2, 32) = 512 CTAs
    conv_mma_kernel<<<cgrid, CONV_THREADS, SM_TOTAL>>>(x1, w1h, b1, cbuf);
    ln_half_kernel<<<B * T / 8, 256>>>(cbuf, g1, be1, x2);
    conv_mma_kernel<<<cgrid, CONV_THREADS, SM_TOTAL>>>(x2, w2h, b2, cbuf);
    ln_linear_kernel<<<B * T / 8, 256>>>(cbuf, g2, be2, lw, lb, dur_out);

    cumsum_kernel<<<B, T>>>(dur, cm);
    dim3 egrid(max_len, B);
    expand_kernel<<<egrid, 128>>>(enc, cm, out, max_len);
}

// round 12
// speedup vs baseline: 1.1351x; 1.1351x over previous
#include <cuda_runtime.h>
#include <cuda_fp16.h>
#include <cstdint>

#define B  32
#define T  1024
#define D  512
#define KW 3

// ---- conv GEMM tiles (R10 config: 128x128 CTA, 32x64 warp tiles) ----
#define BM 128
#define BN 128
#define BK 32
#define XS 40            // Xs row stride in fp16 (80B: conflict-free for ldmatrix)
#define WS 136           // Ws row stride in fp16 (272B: conflict-free for ldmatrix.trans)
#define CONV_THREADS 256
#define NCHUNK (D / BK)  // 16
#define NSTAGE 3

// dynamic smem: three stages, each = [X plane][W plane]
#define X_PLANE ((BM + 2) * XS * 2)          // 10400 B
#define W_PLANE (KW * BK * WS * 2)           // 26112 B
#define STAGE   (X_PLANE + W_PLANE)          // 36512 B
#define SM_TOTAL (NSTAGE * STAGE)            // 109536 B (2 CTAs = 219 KB/SM)

// ---- scratch (no runtime allocation allowed) ----
__device__ float  g_conv[(size_t)B * T * D];    // fp32 conv output
__device__ __half g_x1[(size_t)B * T * D];      // enc fp16
__device__ __half g_x2[(size_t)B * T * D];      // LN1 out fp16
__device__ __half g_w1h[KW * D * D];            // weights fp16 (native HIO)
__device__ __half g_w2h[KW * D * D];
__device__ int    g_cum[B * T];

__device__ __forceinline__ uint32_t smem_u32(const void* p) {
    uint32_t a;
    asm("{ .reg .u64 t; cvta.to.shared.u64 t, %1; cvt.u32.u64 %0, t; }" : "=r"(a) : "l"(p));
    return a;
}
__device__ __forceinline__ void cp16(uint32_t dst, const void* src, int szbytes) {
    asm volatile("cp.async.cg.shared.global [%0], [%1], 16, %2;"
                 :: "r"(dst), "l"(src), "r"(szbytes));
}

// ================= conv1d(k=3,SAME) + bias + relu, fp16 mma.sync ===========
__global__ void __launch_bounds__(CONV_THREADS)
conv_mma_kernel(const __half* __restrict__ x,
                const __half* __restrict__ w,   // [tap][c][n]
                const float* __restrict__ bias,
                float* __restrict__ y) {
    extern __shared__ __align__(16) char smem[];

    const int tid  = threadIdx.x;
    const int lane = tid & 31;
    const int wid  = tid >> 5;
    const int wm   = wid >> 1;     // 0..3 -> m offset wm*32
    const int wn   = wid & 1;      // 0..1 -> n offset wn*64
    const int t0   = blockIdx.x * BM;
    const int n0   = blockIdx.y * BN;
    const int b    = blockIdx.z;

    float c[2][8][4];
#pragma unroll
    for (int mt = 0; mt < 2; mt++)
#pragma unroll
        for (int nt = 0; nt < 8; nt++)
#pragma unroll
            for (int i = 0; i < 4; i++) c[mt][nt][i] = 0.f;

    const uint32_t sb = smem_u32(smem);
    const uint32_t a_off = (uint32_t)(((wm * 32 + (lane & 15)) * XS + (lane >> 4) * 8) * 2);
    const uint32_t b_off = (uint32_t)(X_PLANE +
                                      ((lane & 15) * WS + wn * 64 + (lane >> 4) * 8) * 2);

    // ---- async tile loader for chunk c0 into stage st ----
    auto load_chunk = [&](int st, int c0) {
        const uint32_t stb = sb + (uint32_t)(st * STAGE);
        // X plane: 520 16B vectors (row r <-> t = t0 + r - 1, zero pad)
#pragma unroll
        for (int i = 0; i < 3; i++) {
            int idx = tid + i * CONV_THREADS;
            if (idx < (BM + 2) * 4) {
                int row = idx >> 2, u = idx & 3;
                int t = t0 + row - 1;
                int ok = (t >= 0 && t < T);
                int tc = ok ? t : 0;
                cp16(stb + (uint32_t)((row * XS + u * 8) * 2),
                     x + ((size_t)(b * T + tc) * D + c0 + u * 8),
                     ok ? 16 : 0);
            }
        }
        // W plane: [tap][k 0..31][n 0..127], 1536 16B vectors
        const uint32_t wbsm = stb + (uint32_t)X_PLANE;
#pragma unroll
        for (int i = 0; i < 6; i++) {
            int idx = tid + i * CONV_THREADS;
            int r = idx >> 4, u = idx & 15;        // r = tap*32+k
            int tap = r >> 5, k = r & 31;
            cp16(wbsm + (uint32_t)((r * WS + u * 8) * 2),
                 w + ((size_t)(tap * D + c0 + k) * D + n0 + u * 8), 16);
        }
        asm volatile("cp.async.commit_group;");
    };

    load_chunk(0, 0);
    load_chunk(1, BK);

#pragma unroll 1
    for (int it = 0; it < NCHUNK; it++) {
        const int st = it % NSTAGE;
        if (it < NCHUNK - 1)
            asm volatile("cp.async.wait_group 1;");
        else
            asm volatile("cp.async.wait_group 0;");
        // single barrier: stage st ready for all warps AND stage (it+2)%3
        // (computed at it-1) is free to overwrite
        __syncthreads();

        if (it + 2 < NCHUNK)
            load_chunk((it + 2) % NSTAGE, (it + 2) * BK);

        const uint32_t abase = sb + (uint32_t)(st * STAGE) + a_off;
        const uint32_t bbase = sb + (uint32_t)(st * STAGE) + b_off;

#pragma unroll
        for (int tap = 0; tap < KW; tap++) {
#pragma unroll
            for (int ks = 0; ks < 2; ks++) {
                uint32_t a[2][4];
#pragma unroll
                for (int mt = 0; mt < 2; mt++) {
                    uint32_t addr = abase + (uint32_t)((mt * 16 + tap) * XS * 2 + ks * 32);
                    asm volatile(
                        "ldmatrix.sync.aligned.m8n8.x4.shared.b16 {%0,%1,%2,%3}, [%4];"
                        : "=r"(a[mt][0]), "=r"(a[mt][1]), "=r"(a[mt][2]), "=r"(a[mt][3])
                        : "r"(addr));
                }
                uint32_t bf[4][4];
#pragma unroll
                for (int q = 0; q < 4; q++) {
                    uint32_t addr = bbase +
                        (uint32_t)((tap * 32 + ks * 16) * WS * 2 + q * 32);
                    asm volatile(
                        "ldmatrix.sync.aligned.m8n8.x4.trans.shared.b16 {%0,%1,%2,%3}, [%4];"
                        : "=r"(bf[q][0]), "=r"(bf[q][1]), "=r"(bf[q][2]), "=r"(bf[q][3])
                        : "r"(addr));
                }
#pragma unroll
                for (int mt = 0; mt < 2; mt++)
#pragma unroll
                    for (int nt = 0; nt < 8; nt++) {
                        int q = nt >> 1, h = (nt & 1) * 2;
                        asm volatile(
                            "mma.sync.aligned.m16n8k16.row.col.f32.f16.f16.f32 "
                            "{%0,%1,%2,%3}, {%4,%5,%6,%7}, {%8,%9}, {%0,%1,%2,%3};"
                            : "+f"(c[mt][nt][0]), "+f"(c[mt][nt][1]),
                              "+f"(c[mt][nt][2]), "+f"(c[mt][nt][3])
                            : "r"(a[mt][0]), "r"(a[mt][1]), "r"(a[mt][2]), "r"(a[mt][3]),
                              "r"(bf[q][h]), "r"(bf[q][h + 1]));
                    }
            }
        }
    }

    // ---- epilogue: bias + relu, fp32 store ----
    const int gid = lane >> 2, tig = lane & 3;
#pragma unroll
    for (int mt = 0; mt < 2; mt++) {
        int row0 = t0 + wm * 32 + mt * 16 + gid;
#pragma unroll
        for (int nt = 0; nt < 8; nt++) {
            int col = n0 + wn * 64 + nt * 8 + tig * 2;
            float bx = bias[col], by = bias[col + 1];
            float2 o0, o1;
            o0.x = fmaxf(c[mt][nt][0] + bx, 0.f);
            o0.y = fmaxf(c[mt][nt][1] + by, 0.f);
            o1.x = fmaxf(c[mt][nt][2] + bx, 0.f);
            o1.y = fmaxf(c[mt][nt][3] + by, 0.f);
            *reinterpret_cast<float2*>(y + ((size_t)(b * T + row0)) * D + col) = o0;
            *reinterpret_cast<float2*>(y + ((size_t)(b * T + row0 + 8)) * D + col) = o1;
        }
    }
}

// ================= fp32 -> fp16 (enc) =================
__global__ void __launch_bounds__(256)
cvt_half_kernel(const float4* __restrict__ x, uint2* __restrict__ y, int n4) {
    int i = blockIdx.x * 256 + threadIdx.x;
    if (i < n4) {
        float4 v = x[i];
        __half2 a = __floats2half2_rn(v.x, v.y);
        __half2 b = __floats2half2_rn(v.z, v.w);
        uint2 o;
        o.x = reinterpret_cast<const unsigned&>(a);
        o.y = reinterpret_cast<const unsigned&>(b);
        y[i] = o;
    }
}

// ================= fp32 -> fp16, both weight tensors in one launch ==========
__global__ void __launch_bounds__(256)
cvt_w_kernel(const float4* __restrict__ wa, uint2* __restrict__ oa,
             const float4* __restrict__ wb, uint2* __restrict__ ob, int n4) {
    int i = blockIdx.x * 256 + threadIdx.x;
    const float4* src = blockIdx.y ? wb : wa;
    uint2* dst        = blockIdx.y ? ob : oa;
    if (i < n4) {
        float4 v = src[i];
        __half2 a = __floats2half2_rn(v.x, v.y);
        __half2 b = __floats2half2_rn(v.z, v.w);
        uint2 o;
        o.x = reinterpret_cast<const unsigned&>(a);
        o.y = reinterpret_cast<const unsigned&>(b);
        dst[i] = o;
    }
}

// ================= LayerNorm (fp32 in) -> fp16 out =================
__global__ void __launch_bounds__(256)
ln_half_kernel(const float* __restrict__ x, const float* __restrict__ gw,
               const float* __restrict__ gb, __half* __restrict__ y) {
    const int row  = blockIdx.x * 8 + (threadIdx.x >> 5);
    const int lane = threadIdx.x & 31;
    const float4* xr = reinterpret_cast<const float4*>(x) + (size_t)row * (D / 4);
    float4 v[4];
    float s = 0.f, sq = 0.f;
#pragma unroll
    for (int i = 0; i < 4; i++) {
        float4 t = xr[i * 32 + lane];
        v[i] = t;
        s  += t.x + t.y + t.z + t.w;
        sq += t.x * t.x + t.y * t.y + t.z * t.z + t.w * t.w;
    }
#pragma unroll
    for (int o = 16; o > 0; o >>= 1) {
        s  += __shfl_xor_sync(0xffffffffu, s, o);
        sq += __shfl_xor_sync(0xffffffffu, sq, o);
    }
    const float mu = s * (1.0f / D);
    const float rs = rsqrtf(sq * (1.0f / D) - mu * mu + 1e-5f);
    const float4* gv = reinterpret_cast<const float4*>(gw);
    const float4* bv = reinterpret_cast<const float4*>(gb);
    uint2* yr = reinterpret_cast<uint2*>(y + (size_t)row * D);
#pragma unroll
    for (int i = 0; i < 4; i++) {
        float4 g = gv[i * 32 + lane], bb = bv[i * 32 + lane], t = v[i];
        float4 o;
        o.x = (t.x - mu) * rs * g.x + bb.x;
        o.y = (t.y - mu) * rs * g.y + bb.y;
        o.z = (t.z - mu) * rs * g.z + bb.z;
        o.w = (t.w - mu) * rs * g.w + bb.w;
        __half2 p0 = __floats2half2_rn(o.x, o.y);
        __half2 p1 = __floats2half2_rn(o.z, o.w);
        uint2 u;
        u.x = reinterpret_cast<const unsigned&>(p0);
        u.y = reinterpret_cast<const unsigned&>(p1);
        yr[i * 32 + lane] = u;
    }
}

// ================= LayerNorm + linear(512->1) fused =================
__global__ void __launch_bounds__(256)
ln_linear_kernel(const float* __restrict__ x, const float* __restrict__ gw,
                 const float* __restrict__ gb, const float* __restrict__ lw,
                 const float* __restrict__ lb, float* __restrict__ dur_out) {
    const int row  = blockIdx.x * 8 + (threadIdx.x >> 5);
    const int lane = threadIdx.x & 31;
    const float4* xr = reinterpret_cast<const float4*>(x) + (size_t)row * (D / 4);
    float4 v[4];
    float s = 0.f, sq = 0.f;
#pragma unroll
    for (int i = 0; i < 4; i++) {
        float4 t = xr[i * 32 + lane];
        v[i] = t;
        s  += t.x + t.y + t.z + t.w;
        sq += t.x * t.x + t.y * t.y + t.z * t.z + t.w * t.w;
    }
#pragma unroll
    for (int o = 16; o > 0; o >>= 1) {
        s  += __shfl_xor_sync(0xffffffffu, s, o);
        sq += __shfl_xor_sync(0xffffffffu, sq, o);
    }
    const float mu = s * (1.0f / D);
    const float rs = rsqrtf(sq * (1.0f / D) - mu * mu + 1e-5f);
    const float4* gv = reinterpret_cast<const float4*>(gw);
    const float4* bv = reinterpret_cast<const float4*>(gb);
    const float4* wv = reinterpret_cast<const float4*>(lw);
    float dot = 0.f;
#pragma unroll
    for (int i = 0; i < 4; i++) {
        float4 g = gv[i * 32 + lane], bb = bv[i * 32 + lane];
        float4 w = wv[i * 32 + lane], t = v[i];
        dot += ((t.x - mu) * rs * g.x + bb.x) * w.x;
        dot += ((t.y - mu) * rs * g.y + bb.y) * w.y;
        dot += ((t.z - mu) * rs * g.z + bb.z) * w.z;
        dot += ((t.w - mu) * rs * g.w + bb.w) * w.w;
    }
#pragma unroll
    for (int o = 16; o > 0; o >>= 1)
        dot += __shfl_xor_sync(0xffffffffu, dot, o);
    if (lane == 0) dur_out[row] = dot + lb[0];
}

// ================= per-batch inclusive cumsum =================
__global__ void __launch_bounds__(T)
cumsum_kernel(const int* __restrict__ dur, int* __restrict__ cum) {
    __shared__ int s[T];
    const int b = blockIdx.x, t = threadIdx.x;
    s[t] = dur[b * T + t];
    __syncthreads();
#pragma unroll
    for (int off = 1; off < T; off <<= 1) {
        int add = (t >= off) ? s[t - off] : 0;
        __syncthreads();
        s[t] += add;
        __syncthreads();
    }
    cum[b * T + t] = s[t];
}

// ================= length-regulation gather =================
__global__ void __launch_bounds__(128)
expand_kernel(const float* __restrict__ enc, const int* __restrict__ cum,
              float* __restrict__ out, int max_len) {
    const int j    = blockIdx.x;
    const int b    = blockIdx.y;
    const int lane = threadIdx.x;
    const int* c = cum + b * T;
    const int total = c[T - 1];
    float4 v = make_float4(0.f, 0.f, 0.f, 0.f);
    if (j < total) {
        int lo = 0, hi = T - 1;
        while (lo < hi) {
            int mid = (lo + hi) >> 1;
            if (c[mid] > j) hi = mid; else lo = mid + 1;
        }
        v = reinterpret_cast<const float4*>(enc + (size_t)(b * T + lo) * D)[lane];
    }
    reinterpret_cast<float4*>(out + ((size_t)b * max_len + j) * D)[lane] = v;
}

extern "C" void kernel_launch(void* const* d_in, const int* in_sizes, int n_in,
                              void* d_out, int out_size) {
    const float* enc = (const float*)d_in[0];
    const int*   dur = (const int*)d_in[1];
    const float* w1  = (const float*)d_in[2];
    const float* b1  = (const float*)d_in[3];
    const float* g1  = (const float*)d_in[4];
    const float* be1 = (const float*)d_in[5];
    const float* w2  = (const float*)d_in[6];
    const float* b2  = (const float*)d_in[7];
    const float* g2  = (const float*)d_in[8];
    const float* be2 = (const float*)d_in[9];
    const float* lw  = (const float*)d_in[10];
    const float* lb  = (const float*)d_in[11];

    const int max_len = (out_size - B * T) / (B * D);
    float* out     = (float*)d_out;
    float* dur_out = out + (size_t)B * max_len * D;

    float* cbuf;    cudaGetSymbolAddress((void**)&cbuf, g_conv);
    __half *x1, *x2, *w1h, *w2h;
    cudaGetSymbolAddress((void**)&x1, g_x1);
    cudaGetSymbolAddress((void**)&x2, g_x2);
    cudaGetSymbolAddress((void**)&w1h, g_w1h);
    cudaGetSymbolAddress((void**)&w2h, g_w2h);
    int* cm;        cudaGetSymbolAddress((void**)&cm, g_cum);

    cudaFuncSetAttribute(conv_mma_kernel,
                         cudaFuncAttributeMaxDynamicSharedMemorySize, SM_TOTAL);

    // conversions: enc + both weight tensors to fp16 (native layouts)
    const int nx4 = (B * T * D) / 4;
    cvt_half_kernel<<<nx4 / 256, 256>>>((const float4*)enc, (uint2*)x1, nx4);
    const int nw4 = (KW * D * D) / 4;
    dim3 wgrid((nw4 + 255) / 256, 2);
    cvt_w_kernel<<<wgrid, 256>>>((const float4*)w1, (uint2*)w1h,
                                 (const float4*)w2, (uint2*)w2h, nw4);

    dim3 cgrid(T / BM, D / BN, B);   // (8, 4, 32) = 1024 CTAs
    conv_mma_kernel<<<cgrid, CONV_THREADS, SM_TOTAL>>>(x1, w1h, b1, cbuf);
    ln_half_kernel<<<B * T / 8, 256>>>(cbuf, g1, be1, x2);
    conv_mma_kernel<<<cgrid, CONV_THREADS, SM_TOTAL>>>(x2, w2h, b2, cbuf);
    ln_linear_kernel<<<B * T / 8, 256>>>(cbuf, g2, be2, lw, lb, dur_out);

    cumsum_kernel<<<B, T>>>(dur, cm);
    dim3 egrid(max_len, B);
    expand_kernel<<<egrid, 128>>>(enc, cm, out, max_len);
}

// round 13
// speedup vs baseline: 1.1507x; 1.0137x over previous
#include <cuda_runtime.h>
#include <cuda_fp16.h>
#include <cstdint>

#define B  32
#define T  1024
#define D  512
#define KW 3

// ---- conv GEMM tiles (128x128 CTA, 32x64 warp tiles) ----
#define BM 128
#define BN 128
#define BK 32
#define XS 40            // Xs row stride in fp16 (80B: conflict-free for ldmatrix)
#define WS 136           // Ws row stride in fp16 (272B: conflict-free for ldmatrix.trans)
#define CONV_THREADS 256
#define NCHUNK (D / BK)  // 16
#define NSTAGE 3

// dynamic smem: three stages, each = [X plane][W plane]
#define X_PLANE ((BM + 2) * XS * 2)          // 10400 B
#define W_PLANE (KW * BK * WS * 2)           // 26112 B
#define STAGE   (X_PLANE + W_PLANE)          // 36512 B
#define SM_TOTAL (NSTAGE * STAGE)            // 109536 B (2 CTAs = 219 KB/SM)

// ---- scratch (no runtime allocation allowed) ----
__device__ __half g_h[(size_t)B * T * D];       // conv output fp16 (both convs)
__device__ __half g_x1[(size_t)B * T * D];      // enc fp16
__device__ __half g_x2[(size_t)B * T * D];      // LN1 out fp16
__device__ __half g_w1h[KW * D * D];            // weights fp16 (native HIO)
__device__ __half g_w2h[KW * D * D];
__device__ int    g_cum[B * T];

__device__ __forceinline__ uint32_t smem_u32(const void* p) {
    uint32_t a;
    asm("{ .reg .u64 t; cvta.to.shared.u64 t, %1; cvt.u32.u64 %0, t; }" : "=r"(a) : "l"(p));
    return a;
}
__device__ __forceinline__ void cp16(uint32_t dst, const void* src, int szbytes) {
    asm volatile("cp.async.cg.shared.global [%0], [%1], 16, %2;"
                 :: "r"(dst), "l"(src), "r"(szbytes));
}

// ================= conv1d(k=3,SAME) + bias + relu, fp16 mma.sync, fp16 out =====
__global__ void __launch_bounds__(CONV_THREADS, 2)
conv_mma_kernel(const __half* __restrict__ x,
                const __half* __restrict__ w,   // [tap][c][n]
                const float* __restrict__ bias,
                __half* __restrict__ y) {
    extern __shared__ __align__(16) char smem[];

    const int tid  = threadIdx.x;
    const int lane = tid & 31;
    const int wid  = tid >> 5;
    const int wm   = wid >> 1;     // 0..3 -> m offset wm*32
    const int wn   = wid & 1;      // 0..1 -> n offset wn*64
    const int t0   = blockIdx.x * BM;
    const int n0   = blockIdx.y * BN;
    const int b    = blockIdx.z;

    float c[2][8][4];
#pragma unroll
    for (int mt = 0; mt < 2; mt++)
#pragma unroll
        for (int nt = 0; nt < 8; nt++)
#pragma unroll
            for (int i = 0; i < 4; i++) c[mt][nt][i] = 0.f;

    const uint32_t sb = smem_u32(smem);
    const uint32_t a_off = (uint32_t)(((wm * 32 + (lane & 15)) * XS + (lane >> 4) * 8) * 2);
    const uint32_t b_off = (uint32_t)(X_PLANE +
                                      ((lane & 15) * WS + wn * 64 + (lane >> 4) * 8) * 2);

    // ---- async tile loader for chunk c0 into stage st ----
    auto load_chunk = [&](int st, int c0) {
        const uint32_t stb = sb + (uint32_t)(st * STAGE);
        // X plane: 520 16B vectors (row r <-> t = t0 + r - 1, zero pad)
#pragma unroll
        for (int i = 0; i < 3; i++) {
            int idx = tid + i * CONV_THREADS;
            if (idx < (BM + 2) * 4) {
                int row = idx >> 2, u = idx & 3;
                int t = t0 + row - 1;
                int ok = (t >= 0 && t < T);
                int tc = ok ? t : 0;
                cp16(stb + (uint32_t)((row * XS + u * 8) * 2),
                     x + ((size_t)(b * T + tc) * D + c0 + u * 8),
                     ok ? 16 : 0);
            }
        }
        // W plane: [tap][k 0..31][n 0..127], 1536 16B vectors
        const uint32_t wbsm = stb + (uint32_t)X_PLANE;
#pragma unroll
        for (int i = 0; i < 6; i++) {
            int idx = tid + i * CONV_THREADS;
            int r = idx >> 4, u = idx & 15;        // r = tap*32+k
            int tap = r >> 5, k = r & 31;
            cp16(wbsm + (uint32_t)((r * WS + u * 8) * 2),
                 w + ((size_t)(tap * D + c0 + k) * D + n0 + u * 8), 16);
        }
        asm volatile("cp.async.commit_group;");
    };

    load_chunk(0, 0);
    load_chunk(1, BK);

#pragma unroll 1
    for (int it = 0; it < NCHUNK; it++) {
        const int st = it % NSTAGE;
        if (it < NCHUNK - 1)
            asm volatile("cp.async.wait_group 1;");
        else
            asm volatile("cp.async.wait_group 0;");
        __syncthreads();   // stage st ready; stage (it+2)%3 free to overwrite

        if (it + 2 < NCHUNK)
            load_chunk((it + 2) % NSTAGE, (it + 2) * BK);

        const uint32_t abase = sb + (uint32_t)(st * STAGE) + a_off;
        const uint32_t bbase = sb + (uint32_t)(st * STAGE) + b_off;

#pragma unroll
        for (int tap = 0; tap < KW; tap++) {
#pragma unroll
            for (int ks = 0; ks < 2; ks++) {
                uint32_t a[2][4];
#pragma unroll
                for (int mt = 0; mt < 2; mt++) {
                    uint32_t addr = abase + (uint32_t)((mt * 16 + tap) * XS * 2 + ks * 32);
                    asm volatile(
                        "ldmatrix.sync.aligned.m8n8.x4.shared.b16 {%0,%1,%2,%3}, [%4];"
                        : "=r"(a[mt][0]), "=r"(a[mt][1]), "=r"(a[mt][2]), "=r"(a[mt][3])
                        : "r"(addr));
                }
                uint32_t bf[4][4];
#pragma unroll
                for (int q = 0; q < 4; q++) {
                    uint32_t addr = bbase +
                        (uint32_t)((tap * 32 + ks * 16) * WS * 2 + q * 32);
                    asm volatile(
                        "ldmatrix.sync.aligned.m8n8.x4.trans.shared.b16 {%0,%1,%2,%3}, [%4];"
                        : "=r"(bf[q][0]), "=r"(bf[q][1]), "=r"(bf[q][2]), "=r"(bf[q][3])
                        : "r"(addr));
                }
#pragma unroll
                for (int mt = 0; mt < 2; mt++)
#pragma unroll
                    for (int nt = 0; nt < 8; nt++) {
                        int q = nt >> 1, h = (nt & 1) * 2;
                        asm volatile(
                            "mma.sync.aligned.m16n8k16.row.col.f32.f16.f16.f32 "
                            "{%0,%1,%2,%3}, {%4,%5,%6,%7}, {%8,%9}, {%0,%1,%2,%3};"
                            : "+f"(c[mt][nt][0]), "+f"(c[mt][nt][1]),
                              "+f"(c[mt][nt][2]), "+f"(c[mt][nt][3])
                            : "r"(a[mt][0]), "r"(a[mt][1]), "r"(a[mt][2]), "r"(a[mt][3]),
                              "r"(bf[q][h]), "r"(bf[q][h + 1]));
                    }
            }
        }
    }

    // ---- epilogue: bias + relu, fp16 store ----
    const int gid = lane >> 2, tig = lane & 3;
#pragma unroll
    for (int mt = 0; mt < 2; mt++) {
        int row0 = t0 + wm * 32 + mt * 16 + gid;
#pragma unroll
        for (int nt = 0; nt < 8; nt++) {
            int col = n0 + wn * 64 + nt * 8 + tig * 2;
            float bx = bias[col], by = bias[col + 1];
            __half2 o0 = __floats2half2_rn(fmaxf(c[mt][nt][0] + bx, 0.f),
                                           fmaxf(c[mt][nt][1] + by, 0.f));
            __half2 o1 = __floats2half2_rn(fmaxf(c[mt][nt][2] + bx, 0.f),
                                           fmaxf(c[mt][nt][3] + by, 0.f));
            *reinterpret_cast<__half2*>(y + ((size_t)(b * T + row0)) * D + col) = o0;
            *reinterpret_cast<__half2*>(y + ((size_t)(b * T + row0 + 8)) * D + col) = o1;
        }
    }
}

// ================= fp32 -> fp16 (enc) =================
__global__ void __launch_bounds__(256)
cvt_half_kernel(const float4* __restrict__ x, uint2* __restrict__ y, int n4) {
    int i = blockIdx.x * 256 + threadIdx.x;
    if (i < n4) {
        float4 v = x[i];
        __half2 a = __floats2half2_rn(v.x, v.y);
        __half2 b = __floats2half2_rn(v.z, v.w);
        uint2 o;
        o.x = reinterpret_cast<const unsigned&>(a);
        o.y = reinterpret_cast<const unsigned&>(b);
        y[i] = o;
    }
}

// ================= fp32 -> fp16, both weight tensors in one launch ==========
__global__ void __launch_bounds__(256)
cvt_w_kernel(const float4* __restrict__ wa, uint2* __restrict__ oa,
             const float4* __restrict__ wb, uint2* __restrict__ ob, int n4) {
    int i = blockIdx.x * 256 + threadIdx.x;
    const float4* src = blockIdx.y ? wb : wa;
    uint2* dst        = blockIdx.y ? ob : oa;
    if (i < n4) {
        float4 v = src[i];
        __half2 a = __floats2half2_rn(v.x, v.y);
        __half2 b = __floats2half2_rn(v.z, v.w);
        uint2 o;
        o.x = reinterpret_cast<const unsigned&>(a);
        o.y = reinterpret_cast<const unsigned&>(b);
        dst[i] = o;
    }
}

// ================= LayerNorm (fp16 in) -> fp16 out =================
__global__ void __launch_bounds__(256)
ln_half_kernel(const __half* __restrict__ x, const float* __restrict__ gw,
               const float* __restrict__ gb, __half* __restrict__ y) {
    const int row  = blockIdx.x * 8 + (threadIdx.x >> 5);
    const int lane = threadIdx.x & 31;
    const uint2* xr = reinterpret_cast<const uint2*>(x) + (size_t)row * (D / 4);
    float4 v[4];
    float s = 0.f, sq = 0.f;
#pragma unroll
    for (int i = 0; i < 4; i++) {
        uint2 u = xr[i * 32 + lane];
        float2 fa = __half22float2(reinterpret_cast<const __half2&>(u.x));
        float2 fb = __half22float2(reinterpret_cast<const __half2&>(u.y));
        float4 t = make_float4(fa.x, fa.y, fb.x, fb.y);
        v[i] = t;
        s  += t.x + t.y + t.z + t.w;
        sq += t.x * t.x + t.y * t.y + t.z * t.z + t.w * t.w;
    }
#pragma unroll
    for (int o = 16; o > 0; o >>= 1) {
        s  += __shfl_xor_sync(0xffffffffu, s, o);
        sq += __shfl_xor_sync(0xffffffffu, sq, o);
    }
    const float mu = s * (1.0f / D);
    const float rs = rsqrtf(sq * (1.0f / D) - mu * mu + 1e-5f);
    const float4* gv = reinterpret_cast<const float4*>(gw);
    const float4* bv = reinterpret_cast<const float4*>(gb);
    uint2* yr = reinterpret_cast<uint2*>(y + (size_t)row * D);
#pragma unroll
    for (int i = 0; i < 4; i++) {
        float4 g = gv[i * 32 + lane], bb = bv[i * 32 + lane], t = v[i];
        float4 o;
        o.x = (t.x - mu) * rs * g.x + bb.x;
        o.y = (t.y - mu) * rs * g.y + bb.y;
        o.z = (t.z - mu) * rs * g.z + bb.z;
        o.w = (t.w - mu) * rs * g.w + bb.w;
        __half2 p0 = __floats2half2_rn(o.x, o.y);
        __half2 p1 = __floats2half2_rn(o.z, o.w);
        uint2 u;
        u.x = reinterpret_cast<const unsigned&>(p0);
        u.y = reinterpret_cast<const unsigned&>(p1);
        yr[i * 32 + lane] = u;
    }
}

// ================= LayerNorm + linear(512->1) fused, fp16 in =================
__global__ void __launch_bounds__(256)
ln_linear_kernel(const __half* __restrict__ x, const float* __restrict__ gw,
                 const float* __restrict__ gb, const float* __restrict__ lw,
                 const float* __restrict__ lb, float* __restrict__ dur_out) {
    const int row  = blockIdx.x * 8 + (threadIdx.x >> 5);
    const int lane = threadIdx.x & 31;
    const uint2* xr = reinterpret_cast<const uint2*>(x) + (size_t)row * (D / 4);
    float4 v[4];
    float s = 0.f, sq = 0.f;
#pragma unroll
    for (int i = 0; i < 4; i++) {
        uint2 u = xr[i * 32 + lane];
        float2 fa = __half22float2(reinterpret_cast<const __half2&>(u.x));
        float2 fb = __half22float2(reinterpret_cast<const __half2&>(u.y));
        float4 t = make_float4(fa.x, fa.y, fb.x, fb.y);
        v[i] = t;
        s  += t.x + t.y + t.z + t.w;
        sq += t.x * t.x + t.y * t.y + t.z * t.z + t.w * t.w;
    }
#pragma unroll
    for (int o = 16; o > 0; o >>= 1) {
        s  += __shfl_xor_sync(0xffffffffu, s, o);
        sq += __shfl_xor_sync(0xffffffffu, sq, o);
    }
    const float mu = s * (1.0f / D);
    const float rs = rsqrtf(sq * (1.0f / D) - mu * mu + 1e-5f);
    const float4* gv = reinterpret_cast<const float4*>(gw);
    const float4* bv = reinterpret_cast<const float4*>(gb);
    const float4* wv = reinterpret_cast<const float4*>(lw);
    float dot = 0.f;
#pragma unroll
    for (int i = 0; i < 4; i++) {
        float4 g = gv[i * 32 + lane], bb = bv[i * 32 + lane];
        float4 w = wv[i * 32 + lane], t = v[i];
        dot += ((t.x - mu) * rs * g.x + bb.x) * w.x;
        dot += ((t.y - mu) * rs * g.y + bb.y) * w.y;
        dot += ((t.z - mu) * rs * g.z + bb.z) * w.z;
        dot += ((t.w - mu) * rs * g.w + bb.w) * w.w;
    }
#pragma unroll
    for (int o = 16; o > 0; o >>= 1)
        dot += __shfl_xor_sync(0xffffffffu, dot, o);
    if (lane == 0) dur_out[row] = dot + lb[0];
}

// ================= per-batch inclusive cumsum =================
__global__ void __launch_bounds__(T)
cumsum_kernel(const int* __restrict__ dur, int* __restrict__ cum) {
    __shared__ int s[T];
    const int b = blockIdx.x, t = threadIdx.x;
    s[t] = dur[b * T + t];
    __syncthreads();
#pragma unroll
    for (int off = 1; off < T; off <<= 1) {
        int add = (t >= off) ? s[t - off] : 0;
        __syncthreads();
        s[t] += add;
        __syncthreads();
    }
    cum[b * T + t] = s[t];
}

// ================= length-regulation gather =================
__global__ void __launch_bounds__(128)
expand_kernel(const float* __restrict__ enc, const int* __restrict__ cum,
              float* __restrict__ out, int max_len) {
    const int j    = blockIdx.x;
    const int b    = blockIdx.y;
    const int lane = threadIdx.x;
    const int* c = cum + b * T;
    const int total = c[T - 1];
    float4 v = make_float4(0.f, 0.f, 0.f, 0.f);
    if (j < total) {
        int lo = 0, hi = T - 1;
        while (lo < hi) {
            int mid = (lo + hi) >> 1;
            if (c[mid] > j) hi = mid; else lo = mid + 1;
        }
        v = reinterpret_cast<const float4*>(enc + (size_t)(b * T + lo) * D)[lane];
    }
    reinterpret_cast<float4*>(out + ((size_t)b * max_len + j) * D)[lane] = v;
}

extern "C" void kernel_launch(void* const* d_in, const int* in_sizes, int n_in,
                              void* d_out, int out_size) {
    const float* enc = (const float*)d_in[0];
    const int*   dur = (const int*)d_in[1];
    const float* w1  = (const float*)d_in[2];
    const float* b1  = (const float*)d_in[3];
    const float* g1  = (const float*)d_in[4];
    const float* be1 = (const float*)d_in[5];
    const float* w2  = (const float*)d_in[6];
    const float* b2  = (const float*)d_in[7];
    const float* g2  = (const float*)d_in[8];
    const float* be2 = (const float*)d_in[9];
    const float* lw  = (const float*)d_in[10];
    const float* lb  = (const float*)d_in[11];

    const int max_len = (out_size - B * T) / (B * D);
    float* out     = (float*)d_out;
    float* dur_out = out + (size_t)B * max_len * D;

    __half *hbuf, *x1, *x2, *w1h, *w2h;
    cudaGetSymbolAddress((void**)&hbuf, g_h);
    cudaGetSymbolAddress((void**)&x1, g_x1);
    cudaGetSymbolAddress((void**)&x2, g_x2);
    cudaGetSymbolAddress((void**)&w1h, g_w1h);
    cudaGetSymbolAddress((void**)&w2h, g_w2h);
    int* cm;        cudaGetSymbolAddress((void**)&cm, g_cum);

    cudaFuncSetAttribute(conv_mma_kernel,
                         cudaFuncAttributeMaxDynamicSharedMemorySize, SM_TOTAL);

    // conversions: enc + both weight tensors to fp16 (native layouts)
    const int nx4 = (B * T * D) / 4;
    cvt_half_kernel<<<nx4 / 256, 256>>>((const float4*)enc, (uint2*)x1, nx4);
    const int nw4 = (KW * D * D) / 4;
    dim3 wgrid((nw4 + 255) / 256, 2);
    cvt_w_kernel<<<wgrid, 256>>>((const float4*)w1, (uint2*)w1h,
                                 (const float4*)w2, (uint2*)w2h, nw4);

    dim3 cgrid(T / BM, D / BN, B);   // (8, 4, 32) = 1024 CTAs
    conv_mma_kernel<<<cgrid, CONV_THREADS, SM_TOTAL>>>(x1, w1h, b1, hbuf);
    ln_half_kernel<<<B * T / 8, 256>>>(hbuf, g1, be1, x2);
    conv_mma_kernel<<<cgrid, CONV_THREADS, SM_TOTAL>>>(x2, w2h, b2, hbuf);
    ln_linear_kernel<<<B * T / 8, 256>>>(hbuf, g2, be2, lw, lb, dur_out);

    cumsum_kernel<<<B, T>>>(dur, cm);
    dim3 egrid(max_len, B);
    expand_kernel<<<egrid, 128>>>(enc, cm, out, max_len);
}

// round 14
// speedup vs baseline: 1.3075x; 1.1363x over previous
#include <cuda_runtime.h>
#include <cuda_fp16.h>
#include <cstdint>

#define B  32
#define T  1024
#define D  512
#define KW 3

// ---- conv GEMM tiles (128x128 CTA, 32x64 warp tiles) ----
#define BM 128
#define BN 128
#define BK 32
#define XS 40            // Xs row stride in fp16 (80B: conflict-free for ldmatrix)
#define WS 136           // Ws row stride in fp16 (272B: conflict-free for ldmatrix.trans)
#define CONV_THREADS 256
#define NCHUNK (D / BK)  // 16
#define NSTAGE 3
#define MTILES (T / BM)  // 8 conv tiles along x

// dynamic smem: three stages, each = [X plane][W plane]
#define X_PLANE ((BM + 2) * XS * 2)          // 10400 B
#define W_PLANE (KW * BK * WS * 2)           // 26112 B
#define STAGE   (X_PLANE + W_PLANE)          // 36512 B
#define SM_TOTAL (NSTAGE * STAGE)            // 109536 B (2 CTAs = 219 KB/SM)

// ---- scratch (no runtime allocation allowed) ----
__device__ __half g_h[(size_t)B * T * D];       // conv output fp16 (both convs)
__device__ __half g_x1[(size_t)B * T * D];      // enc fp16
__device__ __half g_x2[(size_t)B * T * D];      // LN1 out fp16
__device__ __half g_w1h[KW * D * D];            // weights fp16 (native HIO)
__device__ __half g_w2h[KW * D * D];
__device__ int    g_cum[B * T];

__device__ __forceinline__ uint32_t smem_u32(const void* p) {
    uint32_t a;
    asm("{ .reg .u64 t; cvta.to.shared.u64 t, %1; cvt.u32.u64 %0, t; }" : "=r"(a) : "l"(p));
    return a;
}
__device__ __forceinline__ void cp16(uint32_t dst, const void* src, int szbytes) {
    asm volatile("cp.async.cg.shared.global [%0], [%1], 16, %2;"
                 :: "r"(dst), "l"(src), "r"(szbytes));
}

// ================= conv1d(k=3,SAME) + bias + relu, fp16 mma.sync, fp16 out =====
// Blocks with blockIdx.x >= MTILES run the length-regulation expand instead
// (DRAM-bound; overlaps the tensor-bound conv CTAs inside one launch).
__global__ void __launch_bounds__(CONV_THREADS, 2)
conv_mma_kernel(const __half* __restrict__ x,
                const __half* __restrict__ w,   // [tap][c][n]
                const float* __restrict__ bias,
                __half* __restrict__ y,
                const float* __restrict__ enc,  // expand: fp32 encoder
                const int* __restrict__ cum,    // expand: cumsum durations
                float* __restrict__ out,        // expand: [B, max_len, D]
                int max_len) {
    extern __shared__ __align__(16) char smem[];

    // ---------------- expand path ----------------
    if (blockIdx.x >= MTILES) {
        const int b     = blockIdx.z;
        const int part  = (blockIdx.x - MTILES) + MTILES * blockIdx.y;  // 0..31
        const int nparts = (gridDim.x - MTILES) * gridDim.y;            // 32
        const int chunk = (max_len + nparts - 1) / nparts;              // 128
        const int j0    = part * chunk;
        const int wid   = threadIdx.x >> 5;
        const int lane  = threadIdx.x & 31;
        const int* c    = cum + b * T;
        const int total = c[T - 1];
        for (int r = wid; r < chunk; r += CONV_THREADS / 32) {
            int j = j0 + r;
            if (j >= max_len) break;
            float4 v0 = make_float4(0.f, 0.f, 0.f, 0.f);
            float4 v1 = v0, v2 = v0, v3 = v0;
            if (j < total) {
                int lo = 0, hi = T - 1;
                while (lo < hi) {
                    int mid = (lo + hi) >> 1;
                    if (c[mid] > j) hi = mid; else lo = mid + 1;
                }
                const float4* src = reinterpret_cast<const float4*>(
                    enc + ((size_t)(b * T + lo)) * D);
                v0 = src[lane];       v1 = src[lane + 32];
                v2 = src[lane + 64];  v3 = src[lane + 96];
            }
            float4* dst = reinterpret_cast<float4*>(
                out + ((size_t)b * max_len + j) * D);
            dst[lane]      = v0;  dst[lane + 32] = v1;
            dst[lane + 64] = v2;  dst[lane + 96] = v3;
        }
        return;
    }

    // ---------------- conv path ----------------
    const int tid  = threadIdx.x;
    const int lane = tid & 31;
    const int wid  = tid >> 5;
    const int wm   = wid >> 1;     // 0..3 -> m offset wm*32
    const int wn   = wid & 1;      // 0..1 -> n offset wn*64
    const int t0   = blockIdx.x * BM;
    const int n0   = blockIdx.y * BN;
    const int b    = blockIdx.z;

    float c[2][8][4];
#pragma unroll
    for (int mt = 0; mt < 2; mt++)
#pragma unroll
        for (int nt = 0; nt < 8; nt++)
#pragma unroll
            for (int i = 0; i < 4; i++) c[mt][nt][i] = 0.f;

    const uint32_t sb = smem_u32(smem);
    const uint32_t a_off = (uint32_t)(((wm * 32 + (lane & 15)) * XS + (lane >> 4) * 8) * 2);
    const uint32_t b_off = (uint32_t)(X_PLANE +
                                      ((lane & 15) * WS + wn * 64 + (lane >> 4) * 8) * 2);

    auto load_chunk = [&](int st, int c0) {
        const uint32_t stb = sb + (uint32_t)(st * STAGE);
#pragma unroll
        for (int i = 0; i < 3; i++) {
            int idx = tid + i * CONV_THREADS;
            if (idx < (BM + 2) * 4) {
                int row = idx >> 2, u = idx & 3;
                int t = t0 + row - 1;
                int ok = (t >= 0 && t < T);
                int tc = ok ? t : 0;
                cp16(stb + (uint32_t)((row * XS + u * 8) * 2),
                     x + ((size_t)(b * T + tc) * D + c0 + u * 8),
                     ok ? 16 : 0);
            }
        }
        const uint32_t wbsm = stb + (uint32_t)X_PLANE;
#pragma unroll
        for (int i = 0; i < 6; i++) {
            int idx = tid + i * CONV_THREADS;
            int r = idx >> 4, u = idx & 15;        // r = tap*32+k
            int tap = r >> 5, k = r & 31;
            cp16(wbsm + (uint32_t)((r * WS + u * 8) * 2),
                 w + ((size_t)(tap * D + c0 + k) * D + n0 + u * 8), 16);
        }
        asm volatile("cp.async.commit_group;");
    };

    load_chunk(0, 0);
    load_chunk(1, BK);

#pragma unroll 1
    for (int it = 0; it < NCHUNK; it++) {
        const int st = it % NSTAGE;
        if (it < NCHUNK - 1)
            asm volatile("cp.async.wait_group 1;");
        else
            asm volatile("cp.async.wait_group 0;");
        __syncthreads();   // stage st ready; stage (it+2)%3 free to overwrite

        if (it + 2 < NCHUNK)
            load_chunk((it + 2) % NSTAGE, (it + 2) * BK);

        const uint32_t abase = sb + (uint32_t)(st * STAGE) + a_off;
        const uint32_t bbase = sb + (uint32_t)(st * STAGE) + b_off;

#pragma unroll
        for (int tap = 0; tap < KW; tap++) {
#pragma unroll
            for (int ks = 0; ks < 2; ks++) {
                uint32_t a[2][4];
#pragma unroll
                for (int mt = 0; mt < 2; mt++) {
                    uint32_t addr = abase + (uint32_t)((mt * 16 + tap) * XS * 2 + ks * 32);
                    asm volatile(
                        "ldmatrix.sync.aligned.m8n8.x4.shared.b16 {%0,%1,%2,%3}, [%4];"
                        : "=r"(a[mt][0]), "=r"(a[mt][1]), "=r"(a[mt][2]), "=r"(a[mt][3])
                        : "r"(addr));
                }
                uint32_t bf[4][4];
#pragma unroll
                for (int q = 0; q < 4; q++) {
                    uint32_t addr = bbase +
                        (uint32_t)((tap * 32 + ks * 16) * WS * 2 + q * 32);
                    asm volatile(
                        "ldmatrix.sync.aligned.m8n8.x4.trans.shared.b16 {%0,%1,%2,%3}, [%4];"
                        : "=r"(bf[q][0]), "=r"(bf[q][1]), "=r"(bf[q][2]), "=r"(bf[q][3])
                        : "r"(addr));
                }
#pragma unroll
                for (int mt = 0; mt < 2; mt++)
#pragma unroll
                    for (int nt = 0; nt < 8; nt++) {
                        int q = nt >> 1, h = (nt & 1) * 2;
                        asm volatile(
                            "mma.sync.aligned.m16n8k16.row.col.f32.f16.f16.f32 "
                            "{%0,%1,%2,%3}, {%4,%5,%6,%7}, {%8,%9}, {%0,%1,%2,%3};"
                            : "+f"(c[mt][nt][0]), "+f"(c[mt][nt][1]),
                              "+f"(c[mt][nt][2]), "+f"(c[mt][nt][3])
                            : "r"(a[mt][0]), "r"(a[mt][1]), "r"(a[mt][2]), "r"(a[mt][3]),
                              "r"(bf[q][h]), "r"(bf[q][h + 1]));
                    }
            }
        }
    }

    // ---- epilogue: bias + relu, fp16 store ----
    const int gid = lane >> 2, tig = lane & 3;
#pragma unroll
    for (int mt = 0; mt < 2; mt++) {
        int row0 = t0 + wm * 32 + mt * 16 + gid;
#pragma unroll
        for (int nt = 0; nt < 8; nt++) {
            int col = n0 + wn * 64 + nt * 8 + tig * 2;
            float bx = bias[col], by = bias[col + 1];
            __half2 o0 = __floats2half2_rn(fmaxf(c[mt][nt][0] + bx, 0.f),
                                           fmaxf(c[mt][nt][1] + by, 0.f));
            __half2 o1 = __floats2half2_rn(fmaxf(c[mt][nt][2] + bx, 0.f),
                                           fmaxf(c[mt][nt][3] + by, 0.f));
            *reinterpret_cast<__half2*>(y + ((size_t)(b * T + row0)) * D + col) = o0;
            *reinterpret_cast<__half2*>(y + ((size_t)(b * T + row0 + 8)) * D + col) = o1;
        }
    }
}

// ================= fp32 -> fp16 (enc) =================
__global__ void __launch_bounds__(256)
cvt_half_kernel(const float4* __restrict__ x, uint2* __restrict__ y, int n4) {
    int i = blockIdx.x * 256 + threadIdx.x;
    if (i < n4) {
        float4 v = x[i];
        __half2 a = __floats2half2_rn(v.x, v.y);
        __half2 b = __floats2half2_rn(v.z, v.w);
        uint2 o;
        o.x = reinterpret_cast<const unsigned&>(a);
        o.y = reinterpret_cast<const unsigned&>(b);
        y[i] = o;
    }
}

// ================= fp32 -> fp16, both weight tensors in one launch ==========
__global__ void __launch_bounds__(256)
cvt_w_kernel(const float4* __restrict__ wa, uint2* __restrict__ oa,
             const float4* __restrict__ wb, uint2* __restrict__ ob, int n4) {
    int i = blockIdx.x * 256 + threadIdx.x;
    const float4* src = blockIdx.y ? wb : wa;
    uint2* dst        = blockIdx.y ? ob : oa;
    if (i < n4) {
        float4 v = src[i];
        __half2 a = __floats2half2_rn(v.x, v.y);
        __half2 b = __floats2half2_rn(v.z, v.w);
        uint2 o;
        o.x = reinterpret_cast<const unsigned&>(a);
        o.y = reinterpret_cast<const unsigned&>(b);
        dst[i] = o;
    }
}

// ================= LayerNorm (fp16 in) -> fp16 out =================
__global__ void __launch_bounds__(256)
ln_half_kernel(const __half* __restrict__ x, const float* __restrict__ gw,
               const float* __restrict__ gb, __half* __restrict__ y) {
    const int row  = blockIdx.x * 8 + (threadIdx.x >> 5);
    const int lane = threadIdx.x & 31;
    const uint2* xr = reinterpret_cast<const uint2*>(x) + (size_t)row * (D / 4);
    float4 v[4];
    float s = 0.f, sq = 0.f;
#pragma unroll
    for (int i = 0; i < 4; i++) {
        uint2 u = xr[i * 32 + lane];
        float2 fa = __half22float2(reinterpret_cast<const __half2&>(u.x));
        float2 fb = __half22float2(reinterpret_cast<const __half2&>(u.y));
        float4 t = make_float4(fa.x, fa.y, fb.x, fb.y);
        v[i] = t;
        s  += t.x + t.y + t.z + t.w;
        sq += t.x * t.x + t.y * t.y + t.z * t.z + t.w * t.w;
    }
#pragma unroll
    for (int o = 16; o > 0; o >>= 1) {
        s  += __shfl_xor_sync(0xffffffffu, s, o);
        sq += __shfl_xor_sync(0xffffffffu, sq, o);
    }
    const float mu = s * (1.0f / D);
    const float rs = rsqrtf(sq * (1.0f / D) - mu * mu + 1e-5f);
    const float4* gv = reinterpret_cast<const float4*>(gw);
    const float4* bv = reinterpret_cast<const float4*>(gb);
    uint2* yr = reinterpret_cast<uint2*>(y + (size_t)row * D);
#pragma unroll
    for (int i = 0; i < 4; i++) {
        float4 g = gv[i * 32 + lane], bb = bv[i * 32 + lane], t = v[i];
        float4 o;
        o.x = (t.x - mu) * rs * g.x + bb.x;
        o.y = (t.y - mu) * rs * g.y + bb.y;
        o.z = (t.z - mu) * rs * g.z + bb.z;
        o.w = (t.w - mu) * rs * g.w + bb.w;
        __half2 p0 = __floats2half2_rn(o.x, o.y);
        __half2 p1 = __floats2half2_rn(o.z, o.w);
        uint2 u;
        u.x = reinterpret_cast<const unsigned&>(p0);
        u.y = reinterpret_cast<const unsigned&>(p1);
        yr[i * 32 + lane] = u;
    }
}

// ================= LayerNorm + linear(512->1) fused, fp16 in =================
__global__ void __launch_bounds__(256)
ln_linear_kernel(const __half* __restrict__ x, const float* __restrict__ gw,
                 const float* __restrict__ gb, const float* __restrict__ lw,
                 const float* __restrict__ lb, float* __restrict__ dur_out) {
    const int row  = blockIdx.x * 8 + (threadIdx.x >> 5);
    const int lane = threadIdx.x & 31;
    const uint2* xr = reinterpret_cast<const uint2*>(x) + (size_t)row * (D / 4);
    float4 v[4];
    float s = 0.f, sq = 0.f;
#pragma unroll
    for (int i = 0; i < 4; i++) {
        uint2 u = xr[i * 32 + lane];
        float2 fa = __half22float2(reinterpret_cast<const __half2&>(u.x));
        float2 fb = __half22float2(reinterpret_cast<const __half2&>(u.y));
        float4 t = make_float4(fa.x, fa.y, fb.x, fb.y);
        v[i] = t;
        s  += t.x + t.y + t.z + t.w;
        sq += t.x * t.x + t.y * t.y + t.z * t.z + t.w * t.w;
    }
#pragma unroll
    for (int o = 16; o > 0; o >>= 1) {
        s  += __shfl_xor_sync(0xffffffffu, s, o);
        sq += __shfl_xor_sync(0xffffffffu, sq, o);
    }
    const float mu = s * (1.0f / D);
    const float rs = rsqrtf(sq * (1.0f / D) - mu * mu + 1e-5f);
    const float4* gv = reinterpret_cast<const float4*>(gw);
    const float4* bv = reinterpret_cast<const float4*>(gb);
    const float4* wv = reinterpret_cast<const float4*>(lw);
    float dot = 0.f;
#pragma unroll
    for (int i = 0; i < 4; i++) {
        float4 g = gv[i * 32 + lane], bb = bv[i * 32 + lane];
        float4 w = wv[i * 32 + lane], t = v[i];
        dot += ((t.x - mu) * rs * g.x + bb.x) * w.x;
        dot += ((t.y - mu) * rs * g.y + bb.y) * w.y;
        dot += ((t.z - mu) * rs * g.z + bb.z) * w.z;
        dot += ((t.w - mu) * rs * g.w + bb.w) * w.w;
    }
#pragma unroll
    for (int o = 16; o > 0; o >>= 1)
        dot += __shfl_xor_sync(0xffffffffu, dot, o);
    if (lane == 0) dur_out[row] = dot + lb[0];
}

// ================= per-batch inclusive cumsum =================
__global__ void __launch_bounds__(T)
cumsum_kernel(const int* __restrict__ dur, int* __restrict__ cum) {
    __shared__ int s[T];
    const int b = blockIdx.x, t = threadIdx.x;
    s[t] = dur[b * T + t];
    __syncthreads();
#pragma unroll
    for (int off = 1; off < T; off <<= 1) {
        int add = (t >= off) ? s[t - off] : 0;
        __syncthreads();
        s[t] += add;
        __syncthreads();
    }
    cum[b * T + t] = s[t];
}

extern "C" void kernel_launch(void* const* d_in, const int* in_sizes, int n_in,
                              void* d_out, int out_size) {
    const float* enc = (const float*)d_in[0];
    const int*   dur = (const int*)d_in[1];
    const float* w1  = (const float*)d_in[2];
    const float* b1  = (const float*)d_in[3];
    const float* g1  = (const float*)d_in[4];
    const float* be1 = (const float*)d_in[5];
    const float* w2  = (const float*)d_in[6];
    const float* b2  = (const float*)d_in[7];
    const float* g2  = (const float*)d_in[8];
    const float* be2 = (const float*)d_in[9];
    const float* lw  = (const float*)d_in[10];
    const float* lb  = (const float*)d_in[11];

    const int max_len = (out_size - B * T) / (B * D);
    float* out     = (float*)d_out;
    float* dur_out = out + (size_t)B * max_len * D;

    __half *hbuf, *x1, *x2, *w1h, *w2h;
    cudaGetSymbolAddress((void**)&hbuf, g_h);
    cudaGetSymbolAddress((void**)&x1, g_x1);
    cudaGetSymbolAddress((void**)&x2, g_x2);
    cudaGetSymbolAddress((void**)&w1h, g_w1h);
    cudaGetSymbolAddress((void**)&w2h, g_w2h);
    int* cm;        cudaGetSymbolAddress((void**)&cm, g_cum);

    cudaFuncSetAttribute(conv_mma_kernel,
                         cudaFuncAttributeMaxDynamicSharedMemorySize, SM_TOTAL);

    // cumsum first: expand (merged into conv1's grid) depends only on it
    cumsum_kernel<<<B, T>>>(dur, cm);

    // conversions: enc + both weight tensors to fp16 (native layouts)
    const int nx4 = (B * T * D) / 4;
    cvt_half_kernel<<<nx4 / 256, 256>>>((const float4*)enc, (uint2*)x1, nx4);
    const int nw4 = (KW * D * D) / 4;
    dim3 wgrid((nw4 + 255) / 256, 2);
    cvt_w_kernel<<<wgrid, 256>>>((const float4*)w1, (uint2*)w1h,
                                 (const float4*)w2, (uint2*)w2h, nw4);

    // conv1 with fused expand blocks: grid.x doubled, extra blocks do expand
    dim3 cgrid1(2 * MTILES, D / BN, B);   // (16, 4, 32) = 2048 CTAs
    conv_mma_kernel<<<cgrid1, CONV_THREADS, SM_TOTAL>>>(
        x1, w1h, b1, hbuf, enc, cm, out, max_len);
    ln_half_kernel<<<B * T / 8, 256>>>(hbuf, g1, be1, x2);
    dim3 cgrid2(MTILES, D / BN, B);       // (8, 4, 32) conv only
    conv_mma_kernel<<<cgrid2, CONV_THREADS, SM_TOTAL>>>(
        x2, w2h, b2, hbuf, enc, cm, out, 0);
    ln_linear_kernel<<<B * T / 8, 256>>>(hbuf, g2, be2, lw, lb, dur_out);
}

// round 15
// speedup vs baseline: 1.4110x; 1.0791x over previous
#include <cuda_runtime.h>
#include <cuda_fp16.h>
#include <cstdint>

#define B  32
#define T  1024
#define D  512
#define KW 3

// ---- conv GEMM tiles (128x128 CTA, 32x64 warp tiles) ----
#define BM 128
#define BN 128
#define BK 32
#define XS 40            // Xs row stride in fp16 (80B: conflict-free for ldmatrix)
#define WS 136           // Ws row stride in fp16 (272B: conflict-free for ldmatrix.trans)
#define CONV_THREADS 256
#define NCHUNK (D / BK)  // 16
#define NSTAGE 3
#define MTILES (T / BM)  // 8 conv tiles along x

// dynamic smem: three stages, each = [X plane][W plane]
#define X_PLANE ((BM + 2) * XS * 2)          // 10400 B
#define W_PLANE (KW * BK * WS * 2)           // 26112 B
#define STAGE   (X_PLANE + W_PLANE)          // 36512 B
#define SM_TOTAL (NSTAGE * STAGE)            // 109536 B (2 CTAs = 219 KB/SM)

// ---- scratch (no runtime allocation allowed) ----
__device__ __half g_h[(size_t)B * T * D];       // conv output fp16 (both convs)
__device__ __half g_x1[(size_t)B * T * D];      // enc fp16
__device__ __half g_x2[(size_t)B * T * D];      // LN1 out fp16
__device__ __half g_w1h[KW * D * D];            // weights fp16 (native HIO)
__device__ __half g_w2h[KW * D * D];
__device__ int    g_cum[B * T];

__device__ __forceinline__ uint32_t smem_u32(const void* p) {
    uint32_t a;
    asm("{ .reg .u64 t; cvta.to.shared.u64 t, %1; cvt.u32.u64 %0, t; }" : "=r"(a) : "l"(p));
    return a;
}
__device__ __forceinline__ void cp16(uint32_t dst, const void* src, int szbytes) {
    asm volatile("cp.async.cg.shared.global [%0], [%1], 16, %2;"
                 :: "r"(dst), "l"(src), "r"(szbytes));
}

// ---- one expand row: gather enc[b, lo, :] (or zeros) into out row j ----
__device__ __forceinline__ void expand_row_load(const float* __restrict__ enc,
                                                int b, int lo, int lane, bool valid,
                                                float4* v) {
    if (valid) {
        const float4* src = reinterpret_cast<const float4*>(
            enc + ((size_t)(b * T + lo)) * D);
        v[0] = src[lane];       v[1] = src[lane + 32];
        v[2] = src[lane + 64];  v[3] = src[lane + 96];
    } else {
        v[0] = v[1] = v[2] = v[3] = make_float4(0.f, 0.f, 0.f, 0.f);
    }
}
__device__ __forceinline__ void expand_row_store(float* __restrict__ out,
                                                 size_t rowbase, int lane,
                                                 const float4* v) {
    float4* dst = reinterpret_cast<float4*>(out + rowbase);
    __stwt(dst + lane,      v[0]);  __stwt(dst + lane + 32, v[1]);
    __stwt(dst + lane + 64, v[2]);  __stwt(dst + lane + 96, v[3]);
}

// ================= conv1d(k=3,SAME) + bias + relu, fp16 mma.sync, fp16 out =====
// Blocks with blockIdx.x >= MTILES run the length-regulation expand instead
// (DRAM-bound; overlaps the tensor-bound conv CTAs inside one launch).
__global__ void __launch_bounds__(CONV_THREADS, 2)
conv_mma_kernel(const __half* __restrict__ x,
                const __half* __restrict__ w,   // [tap][c][n]
                const float* __restrict__ bias,
                __half* __restrict__ y,
                const float* __restrict__ enc,  // expand: fp32 encoder
                const int* __restrict__ cum,    // expand: cumsum durations
                float* __restrict__ out,        // expand: [B, max_len, D]
                int max_len) {
    extern __shared__ __align__(16) char smem[];

    // ---------------- expand path ----------------
    if (blockIdx.x >= MTILES) {
        const int b      = blockIdx.z;
        const int part   = (blockIdx.x - MTILES) + MTILES * blockIdx.y;  // 0..31
        const int nparts = (gridDim.x - MTILES) * gridDim.y;             // 32
        const int chunk  = (max_len + nparts - 1) / nparts;              // 128
        const int wid    = threadIdx.x >> 5;
        const int lane   = threadIdx.x & 31;
        const int rpw    = (chunk + 7) / 8;                              // 16
        int j    = part * chunk + wid * rpw;                             // warp's rows: consecutive
        int jend = min(j + rpw, max_len);
        if (j >= jend) return;
        const int* c    = cum + b * T;
        const int total = c[T - 1];
        // initial binary search: first t with c[t] > j
        int lo = 0;
        if (j < total) {
            int hi = T - 1;
            while (lo < hi) {
                int mid = (lo + hi) >> 1;
                if (c[mid] > j) hi = mid; else lo = mid + 1;
            }
        }
        // 2-row pipelined copy with monotonic linear advance of lo
        while (j < jend) {
            bool val0 = (j < total);
            if (val0) { while (c[lo] <= j) lo++; }
            int lo0 = lo;
            int j1 = j + 1;
            bool have1 = (j1 < jend);
            bool val1 = have1 && (j1 < total);
            if (val1) { while (c[lo] <= j1) lo++; }
            int lo1 = lo;

            float4 v0[4], v1[4];
            expand_row_load(enc, b, lo0, lane, val0, v0);
            if (have1) expand_row_load(enc, b, lo1, lane, val1, v1);
            expand_row_store(out, ((size_t)b * max_len + j) * D, lane, v0);
            if (have1) expand_row_store(out, ((size_t)b * max_len + j1) * D, lane, v1);
            j += 2;
        }
        return;
    }

    // ---------------- conv path ----------------
    const int tid  = threadIdx.x;
    const int lane = tid & 31;
    const int wid  = tid >> 5;
    const int wm   = wid >> 1;     // 0..3 -> m offset wm*32
    const int wn   = wid & 1;      // 0..1 -> n offset wn*64
    const int t0   = blockIdx.x * BM;
    const int n0   = blockIdx.y * BN;
    const int b    = blockIdx.z;

    float c[2][8][4];
#pragma unroll
    for (int mt = 0; mt < 2; mt++)
#pragma unroll
        for (int nt = 0; nt < 8; nt++)
#pragma unroll
            for (int i = 0; i < 4; i++) c[mt][nt][i] = 0.f;

    const uint32_t sb = smem_u32(smem);
    const uint32_t a_off = (uint32_t)(((wm * 32 + (lane & 15)) * XS + (lane >> 4) * 8) * 2);
    const uint32_t b_off = (uint32_t)(X_PLANE +
                                      ((lane & 15) * WS + wn * 64 + (lane >> 4) * 8) * 2);

    auto load_chunk = [&](int st, int c0) {
        const uint32_t stb = sb + (uint32_t)(st * STAGE);
#pragma unroll
        for (int i = 0; i < 3; i++) {
            int idx = tid + i * CONV_THREADS;
            if (idx < (BM + 2) * 4) {
                int row = idx >> 2, u = idx & 3;
                int t = t0 + row - 1;
                int ok = (t >= 0 && t < T);
                int tc = ok ? t : 0;
                cp16(stb + (uint32_t)((row * XS + u * 8) * 2),
                     x + ((size_t)(b * T + tc) * D + c0 + u * 8),
                     ok ? 16 : 0);
            }
        }
        const uint32_t wbsm = stb + (uint32_t)X_PLANE;
#pragma unroll
        for (int i = 0; i < 6; i++) {
            int idx = tid + i * CONV_THREADS;
            int r = idx >> 4, u = idx & 15;        // r = tap*32+k
            int tap = r >> 5, k = r & 31;
            cp16(wbsm + (uint32_t)((r * WS + u * 8) * 2),
                 w + ((size_t)(tap * D + c0 + k) * D + n0 + u * 8), 16);
        }
        asm volatile("cp.async.commit_group;");
    };

    load_chunk(0, 0);
    load_chunk(1, BK);

#pragma unroll 1
    for (int it = 0; it < NCHUNK; it++) {
        const int st = it % NSTAGE;
        if (it < NCHUNK - 1)
            asm volatile("cp.async.wait_group 1;");
        else
            asm volatile("cp.async.wait_group 0;");
        __syncthreads();   // stage st ready; stage (it+2)%3 free to overwrite

        if (it + 2 < NCHUNK)
            load_chunk((it + 2) % NSTAGE, (it + 2) * BK);

        const uint32_t abase = sb + (uint32_t)(st * STAGE) + a_off;
        const uint32_t bbase = sb + (uint32_t)(st * STAGE) + b_off;

#pragma unroll
        for (int tap = 0; tap < KW; tap++) {
#pragma unroll
            for (int ks = 0; ks < 2; ks++) {
                uint32_t a[2][4];
#pragma unroll
                for (int mt = 0; mt < 2; mt++) {
                    uint32_t addr = abase + (uint32_t)((mt * 16 + tap) * XS * 2 + ks * 32);
                    asm volatile(
                        "ldmatrix.sync.aligned.m8n8.x4.shared.b16 {%0,%1,%2,%3}, [%4];"
                        : "=r"(a[mt][0]), "=r"(a[mt][1]), "=r"(a[mt][2]), "=r"(a[mt][3])
                        : "r"(addr));
                }
                uint32_t bf[4][4];
#pragma unroll
                for (int q = 0; q < 4; q++) {
                    uint32_t addr = bbase +
                        (uint32_t)((tap * 32 + ks * 16) * WS * 2 + q * 32);
                    asm volatile(
                        "ldmatrix.sync.aligned.m8n8.x4.trans.shared.b16 {%0,%1,%2,%3}, [%4];"
                        : "=r"(bf[q][0]), "=r"(bf[q][1]), "=r"(bf[q][2]), "=r"(bf[q][3])
                        : "r"(addr));
                }
#pragma unroll
                for (int mt = 0; mt < 2; mt++)
#pragma unroll
                    for (int nt = 0; nt < 8; nt++) {
                        int q = nt >> 1, h = (nt & 1) * 2;
                        asm volatile(
                            "mma.sync.aligned.m16n8k16.row.col.f32.f16.f16.f32 "
                            "{%0,%1,%2,%3}, {%4,%5,%6,%7}, {%8,%9}, {%0,%1,%2,%3};"
                            : "+f"(c[mt][nt][0]), "+f"(c[mt][nt][1]),
                              "+f"(c[mt][nt][2]), "+f"(c[mt][nt][3])
                            : "r"(a[mt][0]), "r"(a[mt][1]), "r"(a[mt][2]), "r"(a[mt][3]),
                              "r"(bf[q][h]), "r"(bf[q][h + 1]));
                    }
            }
        }
    }

    // ---- epilogue: bias + relu, fp16 store ----
    const int gid = lane >> 2, tig = lane & 3;
#pragma unroll
    for (int mt = 0; mt < 2; mt++) {
        int row0 = t0 + wm * 32 + mt * 16 + gid;
#pragma unroll
        for (int nt = 0; nt < 8; nt++) {
            int col = n0 + wn * 64 + nt * 8 + tig * 2;
            float bx = bias[col], by = bias[col + 1];
            __half2 o0 = __floats2half2_rn(fmaxf(c[mt][nt][0] + bx, 0.f),
                                           fmaxf(c[mt][nt][1] + by, 0.f));
            __half2 o1 = __floats2half2_rn(fmaxf(c[mt][nt][2] + bx, 0.f),
                                           fmaxf(c[mt][nt][3] + by, 0.f));
            *reinterpret_cast<__half2*>(y + ((size_t)(b * T + row0)) * D + col) = o0;
            *reinterpret_cast<__half2*>(y + ((size_t)(b * T + row0 + 8)) * D + col) = o1;
        }
    }
}

// ================= fp32 -> fp16 (enc) =================
__global__ void __launch_bounds__(256)
cvt_half_kernel(const float4* __restrict__ x, uint2* __restrict__ y, int n4) {
    int i = blockIdx.x * 256 + threadIdx.x;
    if (i < n4) {
        float4 v = x[i];
        __half2 a = __floats2half2_rn(v.x, v.y);
        __half2 b = __floats2half2_rn(v.z, v.w);
        uint2 o;
        o.x = reinterpret_cast<const unsigned&>(a);
        o.y = reinterpret_cast<const unsigned&>(b);
        y[i] = o;
    }
}

// ================= fp32 -> fp16, both weight tensors in one launch ==========
__global__ void __launch_bounds__(256)
cvt_w_kernel(const float4* __restrict__ wa, uint2* __restrict__ oa,
             const float4* __restrict__ wb, uint2* __restrict__ ob, int n4) {
    int i = blockIdx.x * 256 + threadIdx.x;
    const float4* src = blockIdx.y ? wb : wa;
    uint2* dst        = blockIdx.y ? ob : oa;
    if (i < n4) {
        float4 v = src[i];
        __half2 a = __floats2half2_rn(v.x, v.y);
        __half2 b = __floats2half2_rn(v.z, v.w);
        uint2 o;
        o.x = reinterpret_cast<const unsigned&>(a);
        o.y = reinterpret_cast<const unsigned&>(b);
        dst[i] = o;
    }
}

// ================= LayerNorm (fp16 in) -> fp16 out =================
__global__ void __launch_bounds__(256)
ln_half_kernel(const __half* __restrict__ x, const float* __restrict__ gw,
               const float* __restrict__ gb, __half* __restrict__ y) {
    const int row  = blockIdx.x * 8 + (threadIdx.x >> 5);
    const int lane = threadIdx.x & 31;
    const uint2* xr = reinterpret_cast<const uint2*>(x) + (size_t)row * (D / 4);
    float4 v[4];
    float s = 0.f, sq = 0.f;
#pragma unroll
    for (int i = 0; i < 4; i++) {
        uint2 u = xr[i * 32 + lane];
        float2 fa = __half22float2(reinterpret_cast<const __half2&>(u.x));
        float2 fb = __half22float2(reinterpret_cast<const __half2&>(u.y));
        float4 t = make_float4(fa.x, fa.y, fb.x, fb.y);
        v[i] = t;
        s  += t.x + t.y + t.z + t.w;
        sq += t.x * t.x + t.y * t.y + t.z * t.z + t.w * t.w;
    }
#pragma unroll
    for (int o = 16; o > 0; o >>= 1) {
        s  += __shfl_xor_sync(0xffffffffu, s, o);
        sq += __shfl_xor_sync(0xffffffffu, sq, o);
    }
    const float mu = s * (1.0f / D);
    const float rs = rsqrtf(sq * (1.0f / D) - mu * mu + 1e-5f);
    const float4* gv = reinterpret_cast<const float4*>(gw);
    const float4* bv = reinterpret_cast<const float4*>(gb);
    uint2* yr = reinterpret_cast<uint2*>(y + (size_t)row * D);
#pragma unroll
    for (int i = 0; i < 4; i++) {
        float4 g = gv[i * 32 + lane], bb = bv[i * 32 + lane], t = v[i];
        float4 o;
        o.x = (t.x - mu) * rs * g.x + bb.x;
        o.y = (t.y - mu) * rs * g.y + bb.y;
        o.z = (t.z - mu) * rs * g.z + bb.z;
        o.w = (t.w - mu) * rs * g.w + bb.w;
        __half2 p0 = __floats2half2_rn(o.x, o.y);
        __half2 p1 = __floats2half2_rn(o.z, o.w);
        uint2 u;
        u.x = reinterpret_cast<const unsigned&>(p0);
        u.y = reinterpret_cast<const unsigned&>(p1);
        yr[i * 32 + lane] = u;
    }
}

// ================= LayerNorm + linear(512->1) fused, fp16 in =================
__global__ void __launch_bounds__(256)
ln_linear_kernel(const __half* __restrict__ x, const float* __restrict__ gw,
                 const float* __restrict__ gb, const float* __restrict__ lw,
                 const float* __restrict__ lb, float* __restrict__ dur_out) {
    const int row  = blockIdx.x * 8 + (threadIdx.x >> 5);
    const int lane = threadIdx.x & 31;
    const uint2* xr = reinterpret_cast<const uint2*>(x) + (size_t)row * (D / 4);
    float4 v[4];
    float s = 0.f, sq = 0.f;
#pragma unroll
    for (int i = 0; i < 4; i++) {
        uint2 u = xr[i * 32 + lane];
        float2 fa = __half22float2(reinterpret_cast<const __half2&>(u.x));
        float2 fb = __half22float2(reinterpret_cast<const __half2&>(u.y));
        float4 t = make_float4(fa.x, fa.y, fb.x, fb.y);
        v[i] = t;
        s  += t.x + t.y + t.z + t.w;
        sq += t.x * t.x + t.y * t.y + t.z * t.z + t.w * t.w;
    }
#pragma unroll
    for (int o = 16; o > 0; o >>= 1) {
        s  += __shfl_xor_sync(0xffffffffu, s, o);
        sq += __shfl_xor_sync(0xffffffffu, sq, o);
    }
    const float mu = s * (1.0f / D);
    const float rs = rsqrtf(sq * (1.0f / D) - mu * mu + 1e-5f);
    const float4* gv = reinterpret_cast<const float4*>(gw);
    const float4* bv = reinterpret_cast<const float4*>(gb);
    const float4* wv = reinterpret_cast<const float4*>(lw);
    float dot = 0.f;
#pragma unroll
    for (int i = 0; i < 4; i++) {
        float4 g = gv[i * 32 + lane], bb = bv[i * 32 + lane];
        float4 w = wv[i * 32 + lane], t = v[i];
        dot += ((t.x - mu) * rs * g.x + bb.x) * w.x;
        dot += ((t.y - mu) * rs * g.y + bb.y) * w.y;
        dot += ((t.z - mu) * rs * g.z + bb.z) * w.z;
        dot += ((t.w - mu) * rs * g.w + bb.w) * w.w;
    }
#pragma unroll
    for (int o = 16; o > 0; o >>= 1)
        dot += __shfl_xor_sync(0xffffffffu, dot, o);
    if (lane == 0) dur_out[row] = dot + lb[0];
}

// ================= per-batch inclusive cumsum =================
__global__ void __launch_bounds__(T)
cumsum_kernel(const int* __restrict__ dur, int* __restrict__ cum) {
    __shared__ int s[T];
    const int b = blockIdx.x, t = threadIdx.x;
    s[t] = dur[b * T + t];
    __syncthreads();
#pragma unroll
    for (int off = 1; off < T; off <<= 1) {
        int add = (t >= off) ? s[t - off] : 0;
        __syncthreads();
        s[t] += add;
        __syncthreads();
    }
    cum[b * T + t] = s[t];
}

extern "C" void kernel_launch(void* const* d_in, const int* in_sizes, int n_in,
                              void* d_out, int out_size) {
    const float* enc = (const float*)d_in[0];
    const int*   dur = (const int*)d_in[1];
    const float* w1  = (const float*)d_in[2];
    const float* b1  = (const float*)d_in[3];
    const float* g1  = (const float*)d_in[4];
    const float* be1 = (const float*)d_in[5];
    const float* w2  = (const float*)d_in[6];
    const float* b2  = (const float*)d_in[7];
    const float* g2  = (const float*)d_in[8];
    const float* be2 = (const float*)d_in[9];
    const float* lw  = (const float*)d_in[10];
    const float* lb  = (const float*)d_in[11];

    const int max_len = (out_size - B * T) / (B * D);
    float* out     = (float*)d_out;
    float* dur_out = out + (size_t)B * max_len * D;

    __half *hbuf, *x1, *x2, *w1h, *w2h;
    cudaGetSymbolAddress((void**)&hbuf, g_h);
    cudaGetSymbolAddress((void**)&x1, g_x1);
    cudaGetSymbolAddress((void**)&x2, g_x2);
    cudaGetSymbolAddress((void**)&w1h, g_w1h);
    cudaGetSymbolAddress((void**)&w2h, g_w2h);
    int* cm;        cudaGetSymbolAddress((void**)&cm, g_cum);

    cudaFuncSetAttribute(conv_mma_kernel,
                         cudaFuncAttributeMaxDynamicSharedMemorySize, SM_TOTAL);

    // cumsum first: expand (merged into conv1's grid) depends only on it
    cumsum_kernel<<<B, T>>>(dur, cm);

    // conversions: enc + both weight tensors to fp16 (native layouts)
    const int nx4 = (B * T * D) / 4;
    cvt_half_kernel<<<nx4 / 256, 256>>>((const float4*)enc, (uint2*)x1, nx4);
    const int nw4 = (KW * D * D) / 4;
    dim3 wgrid((nw4 + 255) / 256, 2);
    cvt_w_kernel<<<wgrid, 256>>>((const float4*)w1, (uint2*)w1h,
                                 (const float4*)w2, (uint2*)w2h, nw4);

    // conv1 with fused expand blocks: grid.x doubled, extra blocks do expand
    dim3 cgrid1(2 * MTILES, D / BN, B);   // (16, 4, 32) = 2048 CTAs
    conv_mma_kernel<<<cgrid1, CONV_THREADS, SM_TOTAL>>>(
        x1, w1h, b1, hbuf, enc, cm, out, max_len);
    ln_half_kernel<<<B * T / 8, 256>>>(hbuf, g1, be1, x2);
    dim3 cgrid2(MTILES, D / BN, B);       // (8, 4, 32) conv only
    conv_mma_kernel<<<cgrid2, CONV_THREADS, SM_TOTAL>>>(
        x2, w2h, b2, hbuf, enc, cm, out, 0);
    ln_linear_kernel<<<B * T / 8, 256>>>(hbuf, g2, be2, lw, lb, dur_out);
}

// round 16
// speedup vs baseline: 1.4428x; 1.0225x over previous
#include <cuda_runtime.h>
#include <cuda_fp16.h>
#include <cstdint>

#define B  32
#define T  1024
#define D  512
#define KW 3

// ---- conv GEMM tiles (128x128 CTA, 32x64 warp tiles) ----
#define BM 128
#define BN 128
#define BK 32
#define XS 40            // Xs row stride in fp16 (80B: conflict-free for ldmatrix)
#define WS 136           // Ws row stride in fp16 (272B: conflict-free for ldmatrix.trans)
#define CONV_THREADS 256
#define NCHUNK (D / BK)  // 16
#define NSTAGE 3
#define MTILES (T / BM)  // 8 conv tiles along x

// dynamic smem: three stages, each = [X plane][W plane]
#define X_PLANE ((BM + 2) * XS * 2)          // 10400 B
#define W_PLANE (KW * BK * WS * 2)           // 26112 B
#define STAGE   (X_PLANE + W_PLANE)          // 36512 B
#define SM_TOTAL (NSTAGE * STAGE)            // 109536 B (2 CTAs = 219 KB/SM)

// ---- scratch (no runtime allocation allowed) ----
__device__ __half g_h[(size_t)B * T * D];       // conv output fp16 (both convs)
__device__ __half g_x1[(size_t)B * T * D];      // enc fp16
__device__ __half g_x2[(size_t)B * T * D];      // LN1 out fp16
__device__ __half g_w1h[KW * D * D];            // weights fp16 (native HIO)
__device__ __half g_w2h[KW * D * D];
__device__ int    g_cum[B * T];

__device__ __forceinline__ uint32_t smem_u32(const void* p) {
    uint32_t a;
    asm("{ .reg .u64 t; cvta.to.shared.u64 t, %1; cvt.u32.u64 %0, t; }" : "=r"(a) : "l"(p));
    return a;
}
__device__ __forceinline__ void cp16(uint32_t dst, const void* src, int szbytes) {
    asm volatile("cp.async.cg.shared.global [%0], [%1], 16, %2;"
                 :: "r"(dst), "l"(src), "r"(szbytes));
}

// ---- one expand row: gather enc[b, lo, :] (or zeros) into out row j ----
__device__ __forceinline__ void expand_row_load(const float* __restrict__ enc,
                                                int b, int lo, int lane, bool valid,
                                                float4* v) {
    if (valid) {
        const float4* src = reinterpret_cast<const float4*>(
            enc + ((size_t)(b * T + lo)) * D);
        v[0] = src[lane];       v[1] = src[lane + 32];
        v[2] = src[lane + 64];  v[3] = src[lane + 96];
    } else {
        v[0] = v[1] = v[2] = v[3] = make_float4(0.f, 0.f, 0.f, 0.f);
    }
}
__device__ __forceinline__ void expand_row_store(float* __restrict__ out,
                                                 size_t rowbase, int lane,
                                                 const float4* v) {
    float4* dst = reinterpret_cast<float4*>(out + rowbase);
    __stwt(dst + lane,      v[0]);  __stwt(dst + lane + 32, v[1]);
    __stwt(dst + lane + 64, v[2]);  __stwt(dst + lane + 96, v[3]);
}

// ================= conv1d(k=3,SAME) + bias + relu, fp16 mma.sync, fp16 out =====
// Blocks with blockIdx.x >= MTILES run the length-regulation expand instead
// (DRAM-bound; overlaps the tensor-bound conv CTAs inside one launch).
__global__ void __launch_bounds__(CONV_THREADS, 2)
conv_mma_kernel(const __half* __restrict__ x,
                const __half* __restrict__ w,   // [tap][c][n]
                const float* __restrict__ bias,
                __half* __restrict__ y,
                const float* __restrict__ enc,  // expand: fp32 encoder
                const int* __restrict__ cum,    // expand: cumsum durations
                float* __restrict__ out,        // expand: [B, max_len, D]
                int max_len) {
    extern __shared__ __align__(16) char smem[];

    // ---------------- expand path ----------------
    if (blockIdx.x >= MTILES) {
        const int b      = blockIdx.z;
        const int part   = (blockIdx.x - MTILES) + MTILES * blockIdx.y;  // 0..31
        const int nparts = (gridDim.x - MTILES) * gridDim.y;             // 32
        const int chunk  = (max_len + nparts - 1) / nparts;              // 128
        const int wid    = threadIdx.x >> 5;
        const int lane   = threadIdx.x & 31;
        const int rpw    = (chunk + 7) / 8;                              // 16
        int j    = part * chunk + wid * rpw;                             // warp's rows: consecutive
        int jend = min(j + rpw, max_len);
        if (j >= jend) return;
        const int* c    = cum + b * T;
        const int total = c[T - 1];
        // initial binary search: first t with c[t] > j
        int lo = 0;
        if (j < total) {
            int hi = T - 1;
            while (lo < hi) {
                int mid = (lo + hi) >> 1;
                if (c[mid] > j) hi = mid; else lo = mid + 1;
            }
        }
        // 2-row pipelined copy with monotonic linear advance of lo
        while (j < jend) {
            bool val0 = (j < total);
            if (val0) { while (c[lo] <= j) lo++; }
            int lo0 = lo;
            int j1 = j + 1;
            bool have1 = (j1 < jend);
            bool val1 = have1 && (j1 < total);
            if (val1) { while (c[lo] <= j1) lo++; }
            int lo1 = lo;

            float4 v0[4], v1[4];
            expand_row_load(enc, b, lo0, lane, val0, v0);
            if (have1) expand_row_load(enc, b, lo1, lane, val1, v1);
            expand_row_store(out, ((size_t)b * max_len + j) * D, lane, v0);
            if (have1) expand_row_store(out, ((size_t)b * max_len + j1) * D, lane, v1);
            j += 2;
        }
        return;
    }

    // ---------------- conv path ----------------
    const int tid  = threadIdx.x;
    const int lane = tid & 31;
    const int wid  = tid >> 5;
    const int wm   = wid >> 1;     // 0..3 -> m offset wm*32
    const int wn   = wid & 1;      // 0..1 -> n offset wn*64
    const int t0   = blockIdx.x * BM;
    const int n0   = blockIdx.y * BN;
    const int b    = blockIdx.z;

    float c[2][8][4];
#pragma unroll
    for (int mt = 0; mt < 2; mt++)
#pragma unroll
        for (int nt = 0; nt < 8; nt++)
#pragma unroll
            for (int i = 0; i < 4; i++) c[mt][nt][i] = 0.f;

    const uint32_t sb = smem_u32(smem);
    const uint32_t a_off = (uint32_t)(((wm * 32 + (lane & 15)) * XS + (lane >> 4) * 8) * 2);
    const uint32_t b_off = (uint32_t)(X_PLANE +
                                      ((lane & 15) * WS + wn * 64 + (lane >> 4) * 8) * 2);

    auto load_chunk = [&](int st, int c0) {
        const uint32_t stb = sb + (uint32_t)(st * STAGE);
#pragma unroll
        for (int i = 0; i < 3; i++) {
            int idx = tid + i * CONV_THREADS;
            if (idx < (BM + 2) * 4) {
                int row = idx >> 2, u = idx & 3;
                int t = t0 + row - 1;
                int ok = (t >= 0 && t < T);
                int tc = ok ? t : 0;
                cp16(stb + (uint32_t)((row * XS + u * 8) * 2),
                     x + ((size_t)(b * T + tc) * D + c0 + u * 8),
                     ok ? 16 : 0);
            }
        }
        const uint32_t wbsm = stb + (uint32_t)X_PLANE;
#pragma unroll
        for (int i = 0; i < 6; i++) {
            int idx = tid + i * CONV_THREADS;
            int r = idx >> 4, u = idx & 15;        // r = tap*32+k
            int tap = r >> 5, k = r & 31;
            cp16(wbsm + (uint32_t)((r * WS + u * 8) * 2),
                 w + ((size_t)(tap * D + c0 + k) * D + n0 + u * 8), 16);
        }
        asm volatile("cp.async.commit_group;");
    };

    load_chunk(0, 0);
    load_chunk(1, BK);

#pragma unroll 1
    for (int it = 0; it < NCHUNK; it++) {
        const int st = it % NSTAGE;
        if (it < NCHUNK - 1)
            asm volatile("cp.async.wait_group 1;");
        else
            asm volatile("cp.async.wait_group 0;");
        __syncthreads();   // stage st ready; stage (it+2)%3 free to overwrite

        if (it + 2 < NCHUNK)
            load_chunk((it + 2) % NSTAGE, (it + 2) * BK);

        const uint32_t abase = sb + (uint32_t)(st * STAGE) + a_off;
        const uint32_t bbase = sb + (uint32_t)(st * STAGE) + b_off;

#pragma unroll
        for (int tap = 0; tap < KW; tap++) {
#pragma unroll
            for (int ks = 0; ks < 2; ks++) {
                uint32_t a[2][4];
#pragma unroll
                for (int mt = 0; mt < 2; mt++) {
                    uint32_t addr = abase + (uint32_t)((mt * 16 + tap) * XS * 2 + ks * 32);
                    asm volatile(
                        "ldmatrix.sync.aligned.m8n8.x4.shared.b16 {%0,%1,%2,%3}, [%4];"
                        : "=r"(a[mt][0]), "=r"(a[mt][1]), "=r"(a[mt][2]), "=r"(a[mt][3])
                        : "r"(addr));
                }
                uint32_t bf[4][4];
#pragma unroll
                for (int q = 0; q < 4; q++) {
                    uint32_t addr = bbase +
                        (uint32_t)((tap * 32 + ks * 16) * WS * 2 + q * 32);
                    asm volatile(
                        "ldmatrix.sync.aligned.m8n8.x4.trans.shared.b16 {%0,%1,%2,%3}, [%4];"
                        : "=r"(bf[q][0]), "=r"(bf[q][1]), "=r"(bf[q][2]), "=r"(bf[q][3])
                        : "r"(addr));
                }
#pragma unroll
                for (int mt = 0; mt < 2; mt++)
#pragma unroll
                    for (int nt = 0; nt < 8; nt++) {
                        int q = nt >> 1, h = (nt & 1) * 2;
                        asm volatile(
                            "mma.sync.aligned.m16n8k16.row.col.f32.f16.f16.f32 "
                            "{%0,%1,%2,%3}, {%4,%5,%6,%7}, {%8,%9}, {%0,%1,%2,%3};"
                            : "+f"(c[mt][nt][0]), "+f"(c[mt][nt][1]),
                              "+f"(c[mt][nt][2]), "+f"(c[mt][nt][3])
                            : "r"(a[mt][0]), "r"(a[mt][1]), "r"(a[mt][2]), "r"(a[mt][3]),
                              "r"(bf[q][h]), "r"(bf[q][h + 1]));
                    }
            }
        }
    }

    // ---- epilogue: bias + relu, fp16 store ----
    const int gid = lane >> 2, tig = lane & 3;
#pragma unroll
    for (int mt = 0; mt < 2; mt++) {
        int row0 = t0 + wm * 32 + mt * 16 + gid;
#pragma unroll
        for (int nt = 0; nt < 8; nt++) {
            int col = n0 + wn * 64 + nt * 8 + tig * 2;
            float bx = bias[col], by = bias[col + 1];
            __half2 o0 = __floats2half2_rn(fmaxf(c[mt][nt][0] + bx, 0.f),
                                           fmaxf(c[mt][nt][1] + by, 0.f));
            __half2 o1 = __floats2half2_rn(fmaxf(c[mt][nt][2] + bx, 0.f),
                                           fmaxf(c[mt][nt][3] + by, 0.f));
            *reinterpret_cast<__half2*>(y + ((size_t)(b * T + row0)) * D + col) = o0;
            *reinterpret_cast<__half2*>(y + ((size_t)(b * T + row0 + 8)) * D + col) = o1;
        }
    }
}

// ================= prep: cumsum + enc->fp16 + weights->fp16, ONE launch =========
// blocks [0,B): per-batch cumsum (256 thr, 4 elems/thread + block scan)
// blocks [B, B+NX): enc convert ; next NW: w1 ; next NW: w2
__global__ void __launch_bounds__(256)
prep_kernel(const int* __restrict__ dur, int* __restrict__ cum,
            const float4* __restrict__ enc4, uint2* __restrict__ x1, int nx4,
            const float4* __restrict__ w1f, uint2* __restrict__ w1h,
            const float4* __restrict__ w2f, uint2* __restrict__ w2h, int nw4) {
    const int nxb = (nx4 + 255) / 256;
    const int nwb = (nw4 + 255) / 256;
    const int bid = blockIdx.x;
    const int tid = threadIdx.x;

    if (bid < B) {
        // ---- cumsum for batch bid ----
        __shared__ int ps[256];
        const int* dp = dur + bid * T;
        int v0 = dp[tid * 4], v1 = dp[tid * 4 + 1],
            v2 = dp[tid * 4 + 2], v3 = dp[tid * 4 + 3];
        int p0 = v0, p1 = p0 + v1, p2 = p1 + v2, p3 = p2 + v3;
        ps[tid] = p3;
        __syncthreads();
        int acc = ps[tid];
#pragma unroll
        for (int off = 1; off < 256; off <<= 1) {
            int add = (tid >= off) ? ps[tid - off] : 0;
            __syncthreads();
            acc += add;
            ps[tid] = acc;
            __syncthreads();
        }
        int excl = acc - p3;     // exclusive prefix of this thread's 4 elems
        int* cp = cum + bid * T;
        cp[tid * 4]     = excl + p0;
        cp[tid * 4 + 1] = excl + p1;
        cp[tid * 4 + 2] = excl + p2;
        cp[tid * 4 + 3] = excl + p3;
        return;
    }

    const float4* src;
    uint2* dst;
    int i, n;
    if (bid < B + nxb) {
        src = enc4; dst = x1; n = nx4; i = (bid - B) * 256 + tid;
    } else if (bid < B + nxb + nwb) {
        src = w1f; dst = w1h; n = nw4; i = (bid - B - nxb) * 256 + tid;
    } else {
        src = w2f; dst = w2h; n = nw4; i = (bid - B - nxb - nwb) * 256 + tid;
    }
    if (i < n) {
        float4 v = src[i];
        __half2 a = __floats2half2_rn(v.x, v.y);
        __half2 b = __floats2half2_rn(v.z, v.w);
        uint2 o;
        o.x = reinterpret_cast<const unsigned&>(a);
        o.y = reinterpret_cast<const unsigned&>(b);
        dst[i] = o;
    }
}

// ================= LayerNorm (fp16 in) -> fp16 out, 2 rows per warp ============
__global__ void __launch_bounds__(256)
ln_half_kernel(const __half* __restrict__ x, const float* __restrict__ gw,
               const float* __restrict__ gb, __half* __restrict__ y) {
    const int warp = threadIdx.x >> 5;
    const int lane = threadIdx.x & 31;
    const int row0 = blockIdx.x * 16 + warp * 2;
    const uint2* xr0 = reinterpret_cast<const uint2*>(x) + (size_t)row0 * (D / 4);
    const uint2* xr1 = xr0 + (D / 4);
    float4 v0[4], v1[4];
    float s0 = 0.f, q0 = 0.f, s1 = 0.f, q1 = 0.f;
#pragma unroll
    for (int i = 0; i < 4; i++) {
        uint2 ua = xr0[i * 32 + lane];
        uint2 ub = xr1[i * 32 + lane];
        float2 a0 = __half22float2(reinterpret_cast<const __half2&>(ua.x));
        float2 a1 = __half22float2(reinterpret_cast<const __half2&>(ua.y));
        float2 b0 = __half22float2(reinterpret_cast<const __half2&>(ub.x));
        float2 b1 = __half22float2(reinterpret_cast<const __half2&>(ub.y));
        v0[i] = make_float4(a0.x, a0.y, a1.x, a1.y);
        v1[i] = make_float4(b0.x, b0.y, b1.x, b1.y);
        s0 += v0[i].x + v0[i].y + v0[i].z + v0[i].w;
        q0 += v0[i].x * v0[i].x + v0[i].y * v0[i].y + v0[i].z * v0[i].z + v0[i].w * v0[i].w;
        s1 += v1[i].x + v1[i].y + v1[i].z + v1[i].w;
        q1 += v1[i].x * v1[i].x + v1[i].y * v1[i].y + v1[i].z * v1[i].z + v1[i].w * v1[i].w;
    }
#pragma unroll
    for (int o = 16; o > 0; o >>= 1) {
        s0 += __shfl_xor_sync(0xffffffffu, s0, o);
        q0 += __shfl_xor_sync(0xffffffffu, q0, o);
        s1 += __shfl_xor_sync(0xffffffffu, s1, o);
        q1 += __shfl_xor_sync(0xffffffffu, q1, o);
    }
    const float mu0 = s0 * (1.0f / D), mu1 = s1 * (1.0f / D);
    const float rs0 = rsqrtf(q0 * (1.0f / D) - mu0 * mu0 + 1e-5f);
    const float rs1 = rsqrtf(q1 * (1.0f / D) - mu1 * mu1 + 1e-5f);
    const float4* gv = reinterpret_cast<const float4*>(gw);
    const float4* bv = reinterpret_cast<const float4*>(gb);
    uint2* y0 = reinterpret_cast<uint2*>(y + (size_t)row0 * D);
    uint2* y1 = y0 + (D / 4) / 1 * 2;  // (row0+1)*D in uint2 units below
    y1 = reinterpret_cast<uint2*>(y + (size_t)(row0 + 1) * D);
#pragma unroll
    for (int i = 0; i < 4; i++) {
        float4 g = gv[i * 32 + lane], bb = bv[i * 32 + lane];
        float4 t0 = v0[i], t1 = v1[i], o0, o1;
        o0.x = (t0.x - mu0) * rs0 * g.x + bb.x;
        o0.y = (t0.y - mu0) * rs0 * g.y + bb.y;
        o0.z = (t0.z - mu0) * rs0 * g.z + bb.z;
        o0.w = (t0.w - mu0) * rs0 * g.w + bb.w;
        o1.x = (t1.x - mu1) * rs1 * g.x + bb.x;
        o1.y = (t1.y - mu1) * rs1 * g.y + bb.y;
        o1.z = (t1.z - mu1) * rs1 * g.z + bb.z;
        o1.w = (t1.w - mu1) * rs1 * g.w + bb.w;
        __half2 p00 = __floats2half2_rn(o0.x, o0.y);
        __half2 p01 = __floats2half2_rn(o0.z, o0.w);
        __half2 p10 = __floats2half2_rn(o1.x, o1.y);
        __half2 p11 = __floats2half2_rn(o1.z, o1.w);
        uint2 u0, u1;
        u0.x = reinterpret_cast<const unsigned&>(p00);
        u0.y = reinterpret_cast<const unsigned&>(p01);
        u1.x = reinterpret_cast<const unsigned&>(p10);
        u1.y = reinterpret_cast<const unsigned&>(p11);
        y0[i * 32 + lane] = u0;
        y1[i * 32 + lane] = u1;
    }
}

// ================= LayerNorm + linear(512->1), fp16 in, 2 rows per warp ========
__global__ void __launch_bounds__(256)
ln_linear_kernel(const __half* __restrict__ x, const float* __restrict__ gw,
                 const float* __restrict__ gb, const float* __restrict__ lw,
                 const float* __restrict__ lb, float* __restrict__ dur_out) {
    const int warp = threadIdx.x >> 5;
    const int lane = threadIdx.x & 31;
    const int row0 = blockIdx.x * 16 + warp * 2;
    const uint2* xr0 = reinterpret_cast<const uint2*>(x) + (size_t)row0 * (D / 4);
    const uint2* xr1 = xr0 + (D / 4);
    float4 v0[4], v1[4];
    float s0 = 0.f, q0 = 0.f, s1 = 0.f, q1 = 0.f;
#pragma unroll
    for (int i = 0; i < 4; i++) {
        uint2 ua = xr0[i * 32 + lane];
        uint2 ub = xr1[i * 32 + lane];
        float2 a0 = __half22float2(reinterpret_cast<const __half2&>(ua.x));
        float2 a1 = __half22float2(reinterpret_cast<const __half2&>(ua.y));
        float2 b0 = __half22float2(reinterpret_cast<const __half2&>(ub.x));
        float2 b1 = __half22float2(reinterpret_cast<const __half2&>(ub.y));
        v0[i] = make_float4(a0.x, a0.y, a1.x, a1.y);
        v1[i] = make_float4(b0.x, b0.y, b1.x, b1.y);
        s0 += v0[i].x + v0[i].y + v0[i].z + v0[i].w;
        q0 += v0[i].x * v0[i].x + v0[i].y * v0[i].y + v0[i].z * v0[i].z + v0[i].w * v0[i].w;
        s1 += v1[i].x + v1[i].y + v1[i].z + v1[i].w;
        q1 += v1[i].x * v1[i].x + v1[i].y * v1[i].y + v1[i].z * v1[i].z + v1[i].w * v1[i].w;
    }
#pragma unroll
    for (int o = 16; o > 0; o >>= 1) {
        s0 += __shfl_xor_sync(0xffffffffu, s0, o);
        q0 += __shfl_xor_sync(0xffffffffu, q0, o);
        s1 += __shfl_xor_sync(0xffffffffu, s1, o);
        q1 += __shfl_xor_sync(0xffffffffu, q1, o);
    }
    const float mu0 = s0 * (1.0f / D), mu1 = s1 * (1.0f / D);
    const float rs0 = rsqrtf(q0 * (1.0f / D) - mu0 * mu0 + 1e-5f);
    const float rs1 = rsqrtf(q1 * (1.0f / D) - mu1 * mu1 + 1e-5f);
    const float4* gv = reinterpret_cast<const float4*>(gw);
    const float4* bv = reinterpret_cast<const float4*>(gb);
    const float4* wv = reinterpret_cast<const float4*>(lw);
    float d0 = 0.f, d1 = 0.f;
#pragma unroll
    for (int i = 0; i < 4; i++) {
        float4 g = gv[i * 32 + lane], bb = bv[i * 32 + lane];
        float4 w = wv[i * 32 + lane], t0 = v0[i], t1 = v1[i];
        d0 += ((t0.x - mu0) * rs0 * g.x + bb.x) * w.x;
        d0 += ((t0.y - mu0) * rs0 * g.y + bb.y) * w.y;
        d0 += ((t0.z - mu0) * rs0 * g.z + bb.z) * w.z;
        d0 += ((t0.w - mu0) * rs0 * g.w + bb.w) * w.w;
        d1 += ((t1.x - mu1) * rs1 * g.x + bb.x) * w.x;
        d1 += ((t1.y - mu1) * rs1 * g.y + bb.y) * w.y;
        d1 += ((t1.z - mu1) * rs1 * g.z + bb.z) * w.z;
        d1 += ((t1.w - mu1) * rs1 * g.w + bb.w) * w.w;
    }
#pragma unroll
    for (int o = 16; o > 0; o >>= 1) {
        d0 += __shfl_xor_sync(0xffffffffu, d0, o);
        d1 += __shfl_xor_sync(0xffffffffu, d1, o);
    }
    if (lane == 0) {
        dur_out[row0]     = d0 + lb[0];
        dur_out[row0 + 1] = d1 + lb[0];
    }
}

extern "C" void kernel_launch(void* const* d_in, const int* in_sizes, int n_in,
                              void* d_out, int out_size) {
    const float* enc = (const float*)d_in[0];
    const int*   dur = (const int*)d_in[1];
    const float* w1  = (const float*)d_in[2];
    const float* b1  = (const float*)d_in[3];
    const float* g1  = (const float*)d_in[4];
    const float* be1 = (const float*)d_in[5];
    const float* w2  = (const float*)d_in[6];
    const float* b2  = (const float*)d_in[7];
    const float* g2  = (const float*)d_in[8];
    const float* be2 = (const float*)d_in[9];
    const float* lw  = (const float*)d_in[10];
    const float* lb  = (const float*)d_in[11];

    const int max_len = (out_size - B * T) / (B * D);
    float* out     = (float*)d_out;
    float* dur_out = out + (size_t)B * max_len * D;

    __half *hbuf, *x1, *x2, *w1h, *w2h;
    cudaGetSymbolAddress((void**)&hbuf, g_h);
    cudaGetSymbolAddress((void**)&x1, g_x1);
    cudaGetSymbolAddress((void**)&x2, g_x2);
    cudaGetSymbolAddress((void**)&w1h, g_w1h);
    cudaGetSymbolAddress((void**)&w2h, g_w2h);
    int* cm;        cudaGetSymbolAddress((void**)&cm, g_cum);

    cudaFuncSetAttribute(conv_mma_kernel,
                         cudaFuncAttributeMaxDynamicSharedMemorySize, SM_TOTAL);

    // single prep launch: cumsum + enc->fp16 + w1/w2->fp16 (all independent)
    const int nx4 = (B * T * D) / 4;
    const int nw4 = (KW * D * D) / 4;
    const int nxb = (nx4 + 255) / 256;
    const int nwb = (nw4 + 255) / 256;
    prep_kernel<<<B + nxb + 2 * nwb, 256>>>(
        dur, cm, (const float4*)enc, (uint2*)x1, nx4,
        (const float4*)w1, (uint2*)w1h, (const float4*)w2, (uint2*)w2h, nw4);

    // conv1 with fused expand blocks: grid.x doubled, extra blocks do expand
    dim3 cgrid1(2 * MTILES, D / BN, B);   // (16, 4, 32) = 2048 CTAs
    conv_mma_kernel<<<cgrid1, CONV_THREADS, SM_TOTAL>>>(
        x1, w1h, b1, hbuf, enc, cm, out, max_len);
    ln_half_kernel<<<B * T / 16, 256>>>(hbuf, g1, be1, x2);
    dim3 cgrid2(MTILES, D / BN, B);       // (8, 4, 32) conv only
    conv_mma_kernel<<<cgrid2, CONV_THREADS, SM_TOTAL>>>(
        x2, w2h, b2, hbuf, enc, cm, out, 0);
    ln_linear_kernel<<<B * T / 16, 256>>>(hbuf, g2, be2, lw, lb, dur_out);
}

// round 17
// speedup vs baseline: 1.4435x; 1.0005x over previous
#include <cuda_runtime.h>
#include <cuda_fp16.h>
#include <cstdint>

#define B  32
#define T  1024
#define D  512
#define KW 3
#define BT (B * T)

// ---- conv GEMM tiles (128x128 CTA, 32x64 warp tiles) ----
#define BM 128
#define BN 128
#define BK 32
#define XS 40            // Xs row stride in fp16 (80B: conflict-free for ldmatrix)
#define WS 136           // Ws row stride in fp16 (272B: conflict-free for ldmatrix.trans)
#define CONV_THREADS 256
#define NCHUNK (D / BK)  // 16
#define NSTAGE 3
#define MTILES (T / BM)  // 8 conv tiles along x

// dynamic smem: three stages, each = [X plane][W plane]
#define X_PLANE ((BM + 2) * XS * 2)          // 10400 B
#define W_PLANE (KW * BK * WS * 2)           // 26112 B
#define STAGE   (X_PLANE + W_PLANE)          // 36512 B
#define SM_TOTAL (NSTAGE * STAGE)            // 109536 B (2 CTAs = 219 KB/SM)

// ---- scratch (no runtime allocation allowed) ----
__device__ __half g_h[(size_t)BT * D];          // conv output fp16 (both convs)
__device__ __half g_x1[(size_t)BT * D];         // enc fp16
__device__ __half g_x2[(size_t)BT * D];         // LN1 out fp16
__device__ __half g_w1h[KW * D * D];            // weights fp16 (native HIO)
__device__ __half g_w2h[KW * D * D];
__device__ int    g_cum[BT];
__device__ float  g_ps[8 * BT];                 // per-(slot,row) partial sums
__device__ float  g_pq[8 * BT];
__device__ float  g_pp[8 * BT];
__device__ float  g_gwc[D];                     // g2*lw combined
__device__ float  g_consts[2];                  // {Sum(g2*lw), Sum(be2*lw)+lb}

__device__ __forceinline__ uint32_t smem_u32(const void* p) {
    uint32_t a;
    asm("{ .reg .u64 t; cvta.to.shared.u64 t, %1; cvt.u32.u64 %0, t; }" : "=r"(a) : "l"(p));
    return a;
}
__device__ __forceinline__ void cp16(uint32_t dst, const void* src, int szbytes) {
    asm volatile("cp.async.cg.shared.global [%0], [%1], 16, %2;"
                 :: "r"(dst), "l"(src), "r"(szbytes));
}

// ---- one expand row: gather enc[b, lo, :] (or zeros) into out row j ----
__device__ __forceinline__ void expand_row_load(const float* __restrict__ enc,
                                                int b, int lo, int lane, bool valid,
                                                float4* v) {
    if (valid) {
        const float4* src = reinterpret_cast<const float4*>(
            enc + ((size_t)(b * T + lo)) * D);
        v[0] = src[lane];       v[1] = src[lane + 32];
        v[2] = src[lane + 64];  v[3] = src[lane + 96];
    } else {
        v[0] = v[1] = v[2] = v[3] = make_float4(0.f, 0.f, 0.f, 0.f);
    }
}
__device__ __forceinline__ void expand_row_store(float* __restrict__ out,
                                                 size_t rowbase, int lane,
                                                 const float4* v) {
    float4* dst = reinterpret_cast<float4*>(out + rowbase);
    __stwt(dst + lane,      v[0]);  __stwt(dst + lane + 32, v[1]);
    __stwt(dst + lane + 64, v[2]);  __stwt(dst + lane + 96, v[3]);
}

// ================= conv1d(k=3,SAME) + bias + relu, fp16 mma.sync, fp16 out =====
// Blocks with blockIdx.x >= MTILES run the length-regulation expand instead.
// do_stats=1 (conv2): epilogue also accumulates per-row (s, q, p) partials for
// the fused LN2+linear, written to disjoint (slot,row) cells (deterministic).
__global__ void __launch_bounds__(CONV_THREADS, 2)
conv_mma_kernel(const __half* __restrict__ x,
                const __half* __restrict__ w,   // [tap][c][n]
                const float* __restrict__ bias,
                __half* __restrict__ y,
                const float* __restrict__ enc,
                const int* __restrict__ cum,
                float* __restrict__ out,
                int max_len,
                const float* __restrict__ gwc,
                float* __restrict__ ps, float* __restrict__ pq,
                float* __restrict__ pp, int do_stats) {
    extern __shared__ __align__(16) char smem[];

    // ---------------- expand path ----------------
    if (blockIdx.x >= MTILES) {
        const int b      = blockIdx.z;
        const int part   = (blockIdx.x - MTILES) + MTILES * blockIdx.y;
        const int nparts = (gridDim.x - MTILES) * gridDim.y;             // 32
        const int chunk  = (max_len + nparts - 1) / nparts;              // 128
        const int wid    = threadIdx.x >> 5;
        const int lane   = threadIdx.x & 31;
        const int rpw    = (chunk + 7) / 8;                              // 16
        int j    = part * chunk + wid * rpw;
        int jend = min(j + rpw, max_len);
        if (j >= jend) return;
        const int* c    = cum + b * T;
        const int total = c[T - 1];
        int lo = 0;
        if (j < total) {
            int hi = T - 1;
            while (lo < hi) {
                int mid = (lo + hi) >> 1;
                if (c[mid] > j) hi = mid; else lo = mid + 1;
            }
        }
        while (j < jend) {
            bool val0 = (j < total);
            if (val0) { while (c[lo] <= j) lo++; }
            int lo0 = lo;
            int j1 = j + 1;
            bool have1 = (j1 < jend);
            bool val1 = have1 && (j1 < total);
            if (val1) { while (c[lo] <= j1) lo++; }
            int lo1 = lo;

            float4 v0[4], v1[4];
            expand_row_load(enc, b, lo0, lane, val0, v0);
            if (have1) expand_row_load(enc, b, lo1, lane, val1, v1);
            expand_row_store(out, ((size_t)b * max_len + j) * D, lane, v0);
            if (have1) expand_row_store(out, ((size_t)b * max_len + j1) * D, lane, v1);
            j += 2;
        }
        return;
    }

    // ---------------- conv path ----------------
    const int tid  = threadIdx.x;
    const int lane = tid & 31;
    const int wid  = tid >> 5;
    const int wm   = wid >> 1;     // 0..3 -> m offset wm*32
    const int wn   = wid & 1;      // 0..1 -> n offset wn*64
    const int t0   = blockIdx.x * BM;
    const int n0   = blockIdx.y * BN;
    const int b    = blockIdx.z;

    float c[2][8][4];
#pragma unroll
    for (int mt = 0; mt < 2; mt++)
#pragma unroll
        for (int nt = 0; nt < 8; nt++)
#pragma unroll
            for (int i = 0; i < 4; i++) c[mt][nt][i] = 0.f;

    const uint32_t sb = smem_u32(smem);
    const uint32_t a_off = (uint32_t)(((wm * 32 + (lane & 15)) * XS + (lane >> 4) * 8) * 2);
    const uint32_t b_off = (uint32_t)(X_PLANE +
                                      ((lane & 15) * WS + wn * 64 + (lane >> 4) * 8) * 2);

    auto load_chunk = [&](int st, int c0) {
        const uint32_t stb = sb + (uint32_t)(st * STAGE);
#pragma unroll
        for (int i = 0; i < 3; i++) {
            int idx = tid + i * CONV_THREADS;
            if (idx < (BM + 2) * 4) {
                int row = idx >> 2, u = idx & 3;
                int t = t0 + row - 1;
                int ok = (t >= 0 && t < T);
                int tc = ok ? t : 0;
                cp16(stb + (uint32_t)((row * XS + u * 8) * 2),
                     x + ((size_t)(b * T + tc) * D + c0 + u * 8),
                     ok ? 16 : 0);
            }
        }
        const uint32_t wbsm = stb + (uint32_t)X_PLANE;
#pragma unroll
        for (int i = 0; i < 6; i++) {
            int idx = tid + i * CONV_THREADS;
            int r = idx >> 4, u = idx & 15;        // r = tap*32+k
            int tap = r >> 5, k = r & 31;
            cp16(wbsm + (uint32_t)((r * WS + u * 8) * 2),
                 w + ((size_t)(tap * D + c0 + k) * D + n0 + u * 8), 16);
        }
        asm volatile("cp.async.commit_group;");
    };

    load_chunk(0, 0);
    load_chunk(1, BK);

#pragma unroll 1
    for (int it = 0; it < NCHUNK; it++) {
        const int st = it % NSTAGE;
        if (it < NCHUNK - 1)
            asm volatile("cp.async.wait_group 1;");
        else
            asm volatile("cp.async.wait_group 0;");
        __syncthreads();   // stage st ready; stage (it+2)%3 free to overwrite

        if (it + 2 < NCHUNK)
            load_chunk((it + 2) % NSTAGE, (it + 2) * BK);

        const uint32_t abase = sb + (uint32_t)(st * STAGE) + a_off;
        const uint32_t bbase = sb + (uint32_t)(st * STAGE) + b_off;

#pragma unroll
        for (int tap = 0; tap < KW; tap++) {
#pragma unroll
            for (int ks = 0; ks < 2; ks++) {
                uint32_t a[2][4];
#pragma unroll
                for (int mt = 0; mt < 2; mt++) {
                    uint32_t addr = abase + (uint32_t)((mt * 16 + tap) * XS * 2 + ks * 32);
                    asm volatile(
                        "ldmatrix.sync.aligned.m8n8.x4.shared.b16 {%0,%1,%2,%3}, [%4];"
                        : "=r"(a[mt][0]), "=r"(a[mt][1]), "=r"(a[mt][2]), "=r"(a[mt][3])
                        : "r"(addr));
                }
                uint32_t bf[4][4];
#pragma unroll
                for (int q = 0; q < 4; q++) {
                    uint32_t addr = bbase +
                        (uint32_t)((tap * 32 + ks * 16) * WS * 2 + q * 32);
                    asm volatile(
                        "ldmatrix.sync.aligned.m8n8.x4.trans.shared.b16 {%0,%1,%2,%3}, [%4];"
                        : "=r"(bf[q][0]), "=r"(bf[q][1]), "=r"(bf[q][2]), "=r"(bf[q][3])
                        : "r"(addr));
                }
#pragma unroll
                for (int mt = 0; mt < 2; mt++)
#pragma unroll
                    for (int nt = 0; nt < 8; nt++) {
                        int q = nt >> 1, h = (nt & 1) * 2;
                        asm volatile(
                            "mma.sync.aligned.m16n8k16.row.col.f32.f16.f16.f32 "
                            "{%0,%1,%2,%3}, {%4,%5,%6,%7}, {%8,%9}, {%0,%1,%2,%3};"
                            : "+f"(c[mt][nt][0]), "+f"(c[mt][nt][1]),
                              "+f"(c[mt][nt][2]), "+f"(c[mt][nt][3])
                            : "r"(a[mt][0]), "r"(a[mt][1]), "r"(a[mt][2]), "r"(a[mt][3]),
                              "r"(bf[q][h]), "r"(bf[q][h + 1]));
                    }
            }
        }
    }

    // ---- epilogue: bias + relu, fp16 store (+ optional LN2-linear partials) ----
    const int gid = lane >> 2, tig = lane & 3;
#pragma unroll
    for (int mt = 0; mt < 2; mt++) {
        int row0 = t0 + wm * 32 + mt * 16 + gid;
        float s0 = 0.f, q0 = 0.f, p0 = 0.f;
        float s1 = 0.f, q1 = 0.f, p1 = 0.f;
#pragma unroll
        for (int nt = 0; nt < 8; nt++) {
            int col = n0 + wn * 64 + nt * 8 + tig * 2;
            float bx = bias[col], by = bias[col + 1];
            float ox = fmaxf(c[mt][nt][0] + bx, 0.f);
            float oy = fmaxf(c[mt][nt][1] + by, 0.f);
            float oz = fmaxf(c[mt][nt][2] + bx, 0.f);
            float ow = fmaxf(c[mt][nt][3] + by, 0.f);
            if (do_stats) {
                float gx = gwc[col], gy = gwc[col + 1];
                s0 += ox + oy;  q0 += ox * ox + oy * oy;  p0 += ox * gx + oy * gy;
                s1 += oz + ow;  q1 += oz * oz + ow * ow;  p1 += oz * gx + ow * gy;
            }
            __half2 o0 = __floats2half2_rn(ox, oy);
            __half2 o1 = __floats2half2_rn(oz, ow);
            *reinterpret_cast<__half2*>(y + ((size_t)(b * T + row0)) * D + col) = o0;
            *reinterpret_cast<__half2*>(y + ((size_t)(b * T + row0 + 8)) * D + col) = o1;
        }
        if (do_stats) {
#pragma unroll
            for (int o = 1; o <= 2; o <<= 1) {
                s0 += __shfl_xor_sync(0xffffffffu, s0, o);
                q0 += __shfl_xor_sync(0xffffffffu, q0, o);
                p0 += __shfl_xor_sync(0xffffffffu, p0, o);
                s1 += __shfl_xor_sync(0xffffffffu, s1, o);
                q1 += __shfl_xor_sync(0xffffffffu, q1, o);
                p1 += __shfl_xor_sync(0xffffffffu, p1, o);
            }
            if (tig == 0) {
                const size_t base = (size_t)(blockIdx.y * 2 + wn) * BT;
                int r0 = b * T + row0;
                ps[base + r0]     = s0;  pq[base + r0]     = q0;  pp[base + r0]     = p0;
                ps[base + r0 + 8] = s1;  pq[base + r0 + 8] = q1;  pp[base + r0 + 8] = p1;
            }
        }
    }
}

// ================= prep: cumsum + converts + LN2-linear constants, ONE launch ==
__global__ void __launch_bounds__(256)
prep_kernel(const int* __restrict__ dur, int* __restrict__ cum,
            const float4* __restrict__ enc4, uint2* __restrict__ x1, int nx4,
            const float4* __restrict__ w1f, uint2* __restrict__ w1h,
            const float4* __restrict__ w2f, uint2* __restrict__ w2h, int nw4,
            const float* __restrict__ g2, const float* __restrict__ be2,
            const float* __restrict__ lw, const float* __restrict__ lb,
            float* __restrict__ gwc, float* __restrict__ consts) {
    const int nxb = (nx4 + 255) / 256;
    const int nwb = (nw4 + 255) / 256;
    const int bid = blockIdx.x;
    const int tid = threadIdx.x;

    if (bid < B) {
        __shared__ int psm[256];
        const int* dp = dur + bid * T;
        int v0 = dp[tid * 4], v1 = dp[tid * 4 + 1],
            v2 = dp[tid * 4 + 2], v3 = dp[tid * 4 + 3];
        int p0 = v0, p1 = p0 + v1, p2 = p1 + v2, p3 = p2 + v3;
        psm[tid] = p3;
        __syncthreads();
        int acc = psm[tid];
#pragma unroll
        for (int off = 1; off < 256; off <<= 1) {
            int add = (tid >= off) ? psm[tid - off] : 0;
            __syncthreads();
            acc += add;
            psm[tid] = acc;
            __syncthreads();
        }
        int excl = acc - p3;
        int* cp = cum + bid * T;
        cp[tid * 4]     = excl + p0;
        cp[tid * 4 + 1] = excl + p1;
        cp[tid * 4 + 2] = excl + p2;
        cp[tid * 4 + 3] = excl + p3;
        return;
    }

    if (bid == B + nxb + 2 * nwb) {
        // LN2-linear constants: gwc = g2*lw ; Sgw = sum(gwc) ; c1 = sum(be2*lw)+lb
        __shared__ float red[16];
        int c = tid * 2;
        float g0 = g2[c] * lw[c], g1 = g2[c + 1] * lw[c + 1];
        gwc[c] = g0; gwc[c + 1] = g1;
        float sg = g0 + g1;
        float sb = be2[c] * lw[c] + be2[c + 1] * lw[c + 1];
#pragma unroll
        for (int o = 16; o > 0; o >>= 1) {
            sg += __shfl_xor_sync(0xffffffffu, sg, o);
            sb += __shfl_xor_sync(0xffffffffu, sb, o);
        }
        if ((tid & 31) == 0) { red[tid >> 5] = sg; red[8 + (tid >> 5)] = sb; }
        __syncthreads();
        if (tid == 0) {
            float Sg = 0.f, Sb = 0.f;
#pragma unroll
            for (int i = 0; i < 8; i++) { Sg += red[i]; Sb += red[8 + i]; }
            consts[0] = Sg;
            consts[1] = Sb + lb[0];
        }
        return;
    }

    const float4* src;
    uint2* dst;
    int i, n;
    if (bid < B + nxb) {
        src = enc4; dst = x1; n = nx4; i = (bid - B) * 256 + tid;
    } else if (bid < B + nxb + nwb) {
        src = w1f; dst = w1h; n = nw4; i = (bid - B - nxb) * 256 + tid;
    } else {
        src = w2f; dst = w2h; n = nw4; i = (bid - B - nxb - nwb) * 256 + tid;
    }
    if (i < n) {
        float4 v = src[i];
        __half2 a = __floats2half2_rn(v.x, v.y);
        __half2 b = __floats2half2_rn(v.z, v.w);
        uint2 o;
        o.x = reinterpret_cast<const unsigned&>(a);
        o.y = reinterpret_cast<const unsigned&>(b);
        dst[i] = o;
    }
}

// ================= LayerNorm (fp16 in) -> fp16 out, 2 rows per warp ============
__global__ void __launch_bounds__(256)
ln_half_kernel(const __half* __restrict__ x, const float* __restrict__ gw,
               const float* __restrict__ gb, __half* __restrict__ y) {
    const int warp = threadIdx.x >> 5;
    const int lane = threadIdx.x & 31;
    const int row0 = blockIdx.x * 16 + warp * 2;
    const uint2* xr0 = reinterpret_cast<const uint2*>(x) + (size_t)row0 * (D / 4);
    const uint2* xr1 = xr0 + (D / 4);
    float4 v0[4], v1[4];
    float s0 = 0.f, q0 = 0.f, s1 = 0.f, q1 = 0.f;
#pragma unroll
    for (int i = 0; i < 4; i++) {
        uint2 ua = xr0[i * 32 + lane];
        uint2 ub = xr1[i * 32 + lane];
        float2 a0 = __half22float2(reinterpret_cast<const __half2&>(ua.x));
        float2 a1 = __half22float2(reinterpret_cast<const __half2&>(ua.y));
        float2 b0 = __half22float2(reinterpret_cast<const __half2&>(ub.x));
        float2 b1 = __half22float2(reinterpret_cast<const __half2&>(ub.y));
        v0[i] = make_float4(a0.x, a0.y, a1.x, a1.y);
        v1[i] = make_float4(b0.x, b0.y, b1.x, b1.y);
        s0 += v0[i].x + v0[i].y + v0[i].z + v0[i].w;
        q0 += v0[i].x * v0[i].x + v0[i].y * v0[i].y + v0[i].z * v0[i].z + v0[i].w * v0[i].w;
        s1 += v1[i].x + v1[i].y + v1[i].z + v1[i].w;
        q1 += v1[i].x * v1[i].x + v1[i].y * v1[i].y + v1[i].z * v1[i].z + v1[i].w * v1[i].w;
    }
#pragma unroll
    for (int o = 16; o > 0; o >>= 1) {
        s0 += __shfl_xor_sync(0xffffffffu, s0, o);
        q0 += __shfl_xor_sync(0xffffffffu, q0, o);
        s1 += __shfl_xor_sync(0xffffffffu, s1, o);
        q1 += __shfl_xor_sync(0xffffffffu, q1, o);
    }
    const float mu0 = s0 * (1.0f / D), mu1 = s1 * (1.0f / D);
    const float rs0 = rsqrtf(q0 * (1.0f / D) - mu0 * mu0 + 1e-5f);
    const float rs1 = rsqrtf(q1 * (1.0f / D) - mu1 * mu1 + 1e-5f);
    const float4* gv = reinterpret_cast<const float4*>(gw);
    const float4* bv = reinterpret_cast<const float4*>(gb);
    uint2* y0 = reinterpret_cast<uint2*>(y + (size_t)row0 * D);
    uint2* y1 = reinterpret_cast<uint2*>(y + (size_t)(row0 + 1) * D);
#pragma unroll
    for (int i = 0; i < 4; i++) {
        float4 g = gv[i * 32 + lane], bb = bv[i * 32 + lane];
        float4 t0 = v0[i], t1 = v1[i], o0, o1;
        o0.x = (t0.x - mu0) * rs0 * g.x + bb.x;
        o0.y = (t0.y - mu0) * rs0 * g.y + bb.y;
        o0.z = (t0.z - mu0) * rs0 * g.z + bb.z;
        o0.w = (t0.w - mu0) * rs0 * g.w + bb.w;
        o1.x = (t1.x - mu1) * rs1 * g.x + bb.x;
        o1.y = (t1.y - mu1) * rs1 * g.y + bb.y;
        o1.z = (t1.z - mu1) * rs1 * g.z + bb.z;
        o1.w = (t1.w - mu1) * rs1 * g.w + bb.w;
        __half2 p00 = __floats2half2_rn(o0.x, o0.y);
        __half2 p01 = __floats2half2_rn(o0.z, o0.w);
        __half2 p10 = __floats2half2_rn(o1.x, o1.y);
        __half2 p11 = __floats2half2_rn(o1.z, o1.w);
        uint2 u0, u1;
        u0.x = reinterpret_cast<const unsigned&>(p00);
        u0.y = reinterpret_cast<const unsigned&>(p01);
        u1.x = reinterpret_cast<const unsigned&>(p10);
        u1.y = reinterpret_cast<const unsigned&>(p11);
        y0[i * 32 + lane] = u0;
        y1[i * 32 + lane] = u1;
    }
}

// ================= finisher: combine partials -> duration output ===============
__global__ void __launch_bounds__(256)
dur_finish_kernel(const float* __restrict__ ps, const float* __restrict__ pq,
                  const float* __restrict__ pp, const float* __restrict__ consts,
                  float* __restrict__ dur_out) {
    int r = blockIdx.x * 256 + threadIdx.x;
    float s = 0.f, q = 0.f, p = 0.f;
#pragma unroll
    for (int sl = 0; sl < 8; sl++) {
        s += ps[(size_t)sl * BT + r];
        q += pq[(size_t)sl * BT + r];
        p += pp[(size_t)sl * BT + r];
    }
    float mu = s * (1.0f / D);
    float rs = rsqrtf(q * (1.0f / D) - mu * mu + 1e-5f);
    dur_out[r] = rs * (p - mu * consts[0]) + consts[1];
}

extern "C" void kernel_launch(void* const* d_in, const int* in_sizes, int n_in,
                              void* d_out, int out_size) {
    const float* enc = (const float*)d_in[0];
    const int*   dur = (const int*)d_in[1];
    const float* w1  = (const float*)d_in[2];
    const float* b1  = (const float*)d_in[3];
    const float* g1  = (const float*)d_in[4];
    const float* be1 = (const float*)d_in[5];
    const float* w2  = (const float*)d_in[6];
    const float* b2  = (const float*)d_in[7];
    const float* g2  = (const float*)d_in[8];
    const float* be2 = (const float*)d_in[9];
    const float* lw  = (const float*)d_in[10];
    const float* lb  = (const float*)d_in[11];

    const int max_len = (out_size - BT) / (B * D);
    float* out     = (float*)d_out;
    float* dur_out = out + (size_t)B * max_len * D;

    __half *hbuf, *x1, *x2, *w1h, *w2h;
    cudaGetSymbolAddress((void**)&hbuf, g_h);
    cudaGetSymbolAddress((void**)&x1, g_x1);
    cudaGetSymbolAddress((void**)&x2, g_x2);
    cudaGetSymbolAddress((void**)&w1h, g_w1h);
    cudaGetSymbolAddress((void**)&w2h, g_w2h);
    int* cm;        cudaGetSymbolAddress((void**)&cm, g_cum);
    float *psb, *pqb, *ppb, *gwc, *cst;
    cudaGetSymbolAddress((void**)&psb, g_ps);
    cudaGetSymbolAddress((void**)&pqb, g_pq);
    cudaGetSymbolAddress((void**)&ppb, g_pp);
    cudaGetSymbolAddress((void**)&gwc, g_gwc);
    cudaGetSymbolAddress((void**)&cst, g_consts);

    cudaFuncSetAttribute(conv_mma_kernel,
                         cudaFuncAttributeMaxDynamicSharedMemorySize, SM_TOTAL);

    // single prep launch: cumsum + enc->fp16 + w1/w2->fp16 + LN2-linear consts
    const int nx4 = (BT * D) / 4;
    const int nw4 = (KW * D * D) / 4;
    const int nxb = (nx4 + 255) / 256;
    const int nwb = (nw4 + 255) / 256;
    prep_kernel<<<B + nxb + 2 * nwb + 1, 256>>>(
        dur, cm, (const float4*)enc, (uint2*)x1, nx4,
        (const float4*)w1, (uint2*)w1h, (const float4*)w2, (uint2*)w2h, nw4,
        g2, be2, lw, lb, gwc, cst);

    // conv1 with fused expand blocks
    dim3 cgrid1(2 * MTILES, D / BN, B);   // (16, 4, 32)
    conv_mma_kernel<<<cgrid1, CONV_THREADS, SM_TOTAL>>>(
        x1, w1h, b1, hbuf, enc, cm, out, max_len, gwc, psb, pqb, ppb, 0);
    ln_half_kernel<<<BT / 16, 256>>>(hbuf, g1, be1, x2);
    // conv2 with fused LN2+linear partials in epilogue
    dim3 cgrid2(MTILES, D / BN, B);       // (8, 4, 32)
    conv_mma_kernel<<<cgrid2, CONV_THREADS, SM_TOTAL>>>(
        x2, w2h, b2, hbuf, enc, cm, out, 0, gwc, psb, pqb, ppb, 1);
    dur_finish_kernel<<<BT / 256, 256>>>(psb, pqb, ppb, cst, dur_out);
}